// round 9
// baseline (speedup 1.0000x reference)
#include <cuda_runtime.h>
#include <math.h>

// ---------------- problem constants ----------------
#define NB    16
#define NCIN  20
#define NWID  64
#define NPIX  65536      // 256*256
#define NLAY  4
#define M1    16
#define M2    16
#define FCH   128
#define NCOUT 20

typedef unsigned long long ull;

// ---- packed f32x2 helpers (FFMA2: 2 MACs per issued instruction) ----
__device__ __forceinline__ ull ffma2(ull a, ull b, ull c) {
    ull d; asm("fma.rn.f32x2 %0, %1, %2, %3;" : "=l"(d) : "l"(a), "l"(b), "l"(c)); return d;
}
__device__ __forceinline__ ull add2(ull a, ull b) {
    ull d; asm("add.rn.f32x2 %0, %1, %2;" : "=l"(d) : "l"(a), "l"(b)); return d;
}
__device__ __forceinline__ ull pk2(float lo, float hi) {
    ull r; asm("mov.b64 %0, {%1,%2};" : "=l"(r) : "f"(lo), "f"(hi)); return r;
}
__device__ __forceinline__ float2 up2(ull v) {
    float2 r; asm("mov.b64 {%0,%1}, %2;" : "=f"(r.x), "=f"(r.y) : "l"(v)); return r;
}

// ---------------- device scratch (no allocations allowed) ----------------
__device__ float  g_h0[NB*NWID*NPIX];          // 256 MB ping
__device__ float  g_h1[NB*NWID*NPIX];          // 256 MB pong
__device__ float2 g_T  [NB*NWID*16*256];       // fwd stage1: [b][i][ky][h]
__device__ float2 g_Xf [32*16*NB*NWID];        // fwd modes:  [kx][ky][b][i]
__device__ float2 g_Xo [NB*NWID*16*32];        // mixed:      [b][o][ky][kx]
__device__ float2 g_Z  [NB*NWID*256*16];       // inv stage1: [b][o][p][ky]
// twiddle tables
__device__ float g_cw[16*256], g_sw[16*256];   // cos/sin(2*pi*ky*w/256)  [ky][w]
__device__ float g_ch[32*256], g_sh[32*256];   // cos/sin(2*pi*kx*h/256)  [k][h], kx = k<16?k:224+k
__device__ float g_chT[256*32], g_shT[256*32]; // transposed [h][k]
// packed DFT-W twiddles: col<16 = even ky (re/im pairs), col>=16 = odd ky
__device__ float g_E[32*128];                  // [col][w<128]

// ---------------- table init (deterministic, cheap) ----------------
__global__ __launch_bounds__(256) void k_init_tables() {
    int id = blockIdx.x * 256 + threadIdx.x;    // 8192 threads
    if (id < 16*256) {
        int ky = id >> 8, w = id & 255;
        float s, c;
        sincospif((float)(ky * w) * (1.0f/128.0f), &s, &c);
        g_cw[id] = c; g_sw[id] = s;
    }
    if (id < 32*256) {
        int k = id >> 8, h = id & 255;
        int kx = (k < 16) ? k : (224 + k);      // rows 0..15 and 240..255
        float s, c;
        sincospif((float)(kx * h) * (1.0f/128.0f), &s, &c);
        g_ch[id] = c;        g_sh[id] = s;
        g_chT[h*32 + k] = c; g_shT[h*32 + k] = s;
    }
    if (id < 32*128) {
        int c = id >> 7, w = id & 127;
        int ky = (c < 16) ? ((c >> 1) << 1) : (((((c - 16) >> 1)) << 1) + 1);
        int comp = c & 1;
        float s, cv;
        sincospif((float)(ky * w) * (1.0f/128.0f), &s, &cv);
        g_E[id] = comp ? -s : cv;               // re: cos, im: -sin
    }
}

// ---------------- lift: h0[b,d,pix] = sum_c x[b,c,pix]*fc0_w[d,c] + fc0_b[d] ----------------
__global__ __launch_bounds__(256) void k_fc0(const float* __restrict__ x,
                                             const float* __restrict__ w,
                                             const float* __restrict__ bias) {
    __shared__ float ws[NWID*NCIN];             // [d][c], 80B row stride (16B aligned)
    __shared__ float bs[NWID];
    int t = threadIdx.x;
    for (int j = t; j < NWID*NCIN; j += 256) ws[j] = w[j];
    if (t < NWID) bs[t] = bias[t];
    __syncthreads();

    int idx = blockIdx.x * 256 + t;
    int b = idx >> 16, pix = idx & 65535;
    ull xin2[10];
#pragma unroll
    for (int q = 0; q < 10; q++) {
        float x0 = x[(size_t)(b*NCIN + 2*q    )*NPIX + pix];
        float x1 = x[(size_t)(b*NCIN + 2*q + 1)*NPIX + pix];
        xin2[q] = pk2(x0, x1);
    }
#pragma unroll 4
    for (int d = 0; d < NWID; d++) {
        const ulonglong2* wp = (const ulonglong2*)(ws + d*NCIN);  // 20 floats = 5 x 16B
        ull a0 = 0ULL, a1 = 0ULL;
#pragma unroll
        for (int q = 0; q < 5; q++) {
            ulonglong2 ww = wp[q];
            a0 = ffma2(xin2[2*q],   ww.x, a0);
            a1 = ffma2(xin2[2*q+1], ww.y, a1);
        }
        float2 u = up2(add2(a0, a1));
        g_h0[(size_t)(b*NWID + d)*NPIX + pix] = u.x + u.y + bs[d];
    }
}

// ---------------- forward DFT over W (radix-2 fold + FMA2-over-w GEMM, shuffle-free) ----
__global__ __launch_bounds__(256) void k_dftw(int srcsel) {
    const float* __restrict__ hin = srcsel ? g_h1 : g_h0;
    __shared__ float Fs[16*276];                // A at +0 (128 w), B at +144; stride 276
    __shared__ float Es[32*136];                // [col][half*68 + wl]
    int t = threadIdx.x;
    int lane = t & 31, warp = t >> 5;

    // phase 1: warps 0..3 fold rows into Fs; warps 4..7 stage twiddles
    if (warp < 4) {
#pragma unroll
        for (int k = 0; k < 4; k++) {
            int r = warp * 4 + k;
            const float4* src4 = (const float4*)(hin + ((size_t)blockIdx.x * 16 + r) * 256);
            float4 lo = src4[lane], hi = src4[lane + 32];
            float4 A = make_float4(lo.x+hi.x, lo.y+hi.y, lo.z+hi.z, lo.w+hi.w);
            float4 B = make_float4(lo.x-hi.x, lo.y-hi.y, lo.z-hi.z, lo.w-hi.w);
            *(float4*)(Fs + r*276 +       lane*4) = A;
            *(float4*)(Fs + r*276 + 144 + lane*4) = B;
        }
    } else {
        int t2 = t - 128;
        for (int j = t2; j < 4096; j += 128) {
            int c = j >> 7, w = j & 127;
            Es[c*136 + (w >> 6)*68 + (w & 63)] = g_E[j];
        }
    }
    __syncthreads();

    // phase 2
    int rloc  = lane & 15;
    int whalf = lane >> 4;                       // 0: w 0..63, 1: w 64..127
    const float* vbase = Fs + rloc*276 + ((warp >= 4) ? 144 : 0) + whalf*64;
    const float* ebase = Es + (warp*4)*136 + whalf*68;

    ull acc[8];
#pragma unroll
    for (int q = 0; q < 8; q++) acc[q] = 0ULL;

#pragma unroll
    for (int it = 0; it < 16; it++) {
        int wl = it * 4;
        ulonglong2 v = *(const ulonglong2*)(vbase + wl);
#pragma unroll
        for (int c = 0; c < 4; c++) {
            ulonglong2 e = *(const ulonglong2*)(ebase + c*136 + wl);
            acc[2*c]   = ffma2(v.x, e.x, acc[2*c]);
            acc[2*c+1] = ffma2(v.y, e.y, acc[2*c+1]);
        }
    }

    float s[4];
#pragma unroll
    for (int c = 0; c < 4; c++) {
        float2 u = up2(add2(acc[2*c], acc[2*c+1]));
        float v = u.x + u.y;
        v += __shfl_xor_sync(0xffffffffu, v, 16);
        s[c] = v;
    }
    if (whalf == 0) {
        int bi = blockIdx.x >> 4;
        int h  = (blockIdx.x & 15) * 16 + rloc;
        int kyA = (warp < 4) ? 4*warp : 4*(warp - 4) + 1;
        g_T[(size_t)bi*4096 + (kyA    )*256 + h] = make_float2(s[0], s[1]);
        g_T[(size_t)bi*4096 + (kyA + 2)*256 + h] = make_float2(s[2], s[3]);
    }
}

// ---------------- forward DFT over H (twiddle rotation recurrence) ----------------
__global__ __launch_bounds__(256) void k_dfth() {
    __shared__ float2 Ts[16*256];                  // [ky][h], 32 KB
    int bi = blockIdx.x;                           // b*64 + i  (1024 blocks)
    int t = threadIdx.x;
    {
        const float4* Tg4 = (const float4*)(g_T + (size_t)bi * 4096);
        float4* Ts4 = (float4*)Ts;
        for (int j = t; j < 2048; j += 256) Ts4[j] = Tg4[j];
    }
    __syncthreads();

    int kx  = t & 31;
    int ky  = t >> 5;                              // 0..7 ; thread also does ky+8
    int b = bi >> 6, i = bi & 63;

    float c0 = g_chT[32 + kx], s0 = g_shT[32 + kx];
    float c = 1.f, s = 0.f;
    float re0 = 0.f, im0 = 0.f, re1 = 0.f, im1 = 0.f;
#pragma unroll 4
    for (int h = 0; h < 256; h++) {
        float2 a  = Ts[ky*256 + h];
        float2 bq = Ts[(ky + 8)*256 + h];
        re0 = fmaf(a.x,  c, fmaf( a.y,  s, re0));
        im0 = fmaf(a.y,  c, fmaf(-a.x,  s, im0));
        re1 = fmaf(bq.x, c, fmaf( bq.y, s, re1));
        im1 = fmaf(bq.y, c, fmaf(-bq.x, s, im1));
        float cn = fmaf(-s, s0, c*c0);
        float sn = fmaf( c, s0, s*c0);
        c = cn; s = sn;
    }
    g_Xf[((size_t)(kx*16 + ky    )*16 + b)*64 + i] = make_float2(re0, im0);
    g_Xf[((size_t)(kx*16 + ky + 8)*16 + b)*64 + i] = make_float2(re1, im1);
}

// ---------------- per-mode complex GEMM: Xo[b,o] = sum_i Xf[b,i] * W[i,o] ----------------
__global__ __launch_bounds__(256) void k_modemix(const float* __restrict__ w1r, const float* __restrict__ w1i,
                                                 const float* __restrict__ w2r, const float* __restrict__ w2i,
                                                 int layer) {
    __shared__ float2 Xs[16*64];                  // [b][i]   8 KB
    __shared__ float2 Ws[64*64];                  // [i][o]  32 KB
    int mode = blockIdx.x;                        // kx*16 + ky (512 blocks)
    int kx = mode >> 4, ky = mode & 15;
    int t = threadIdx.x;

    const float2* Xg = g_Xf + (size_t)mode * 1024;
    for (int j = t; j < 1024; j += 256) Xs[j] = Xg[j];

    const float* wr; const float* wi; int kxp;
    if (kx < 16) { wr = w1r; wi = w1i; kxp = kx; }
    else         { wr = w2r; wi = w2i; kxp = kx - 16; }
    size_t base = (size_t)layer * (NWID*NWID*256) + (size_t)kxp*16 + ky;
    for (int j = t; j < 4096; j += 256) {         // j = i*64 + o, elem stride 256
        Ws[j] = make_float2(wr[base + (size_t)j*256], wi[base + (size_t)j*256]);
    }
    __syncthreads();

#pragma unroll
    for (int r = 0; r < 4; r++) {
        int oid = t + 256*r;                      // b*64 + o
        int b = oid >> 6, o = oid & 63;
        float re = 0.f, im = 0.f;
#pragma unroll 8
        for (int i = 0; i < 64; i++) {
            float2 X = Xs[b*64 + i];
            float2 W = Ws[i*64 + o];
            re = fmaf(X.x, W.x, fmaf(-X.y, W.y, re));
            im = fmaf(X.x, W.y, fmaf( X.y, W.x, im));
        }
        g_Xo[((size_t)(b*64 + o)*16 + ky)*32 + kx] = make_float2(re, im);
    }
}

// ---------------- inverse DFT over H: Z[b,o,p,ky] = (1/65536) sum_kx Xo * e^{+2pi i kx p/256} ----------------
__global__ __launch_bounds__(256) void k_idfth() {
    __shared__ float2 Xs[16*32];                  // [ky][kx], 4 KB
    int bo = blockIdx.x;                          // b*64 + o (1024 blocks)
    int t = threadIdx.x;                          // p
    {
        const float4* Xg4 = (const float4*)(g_Xo + (size_t)bo * 512);
        float4* Xs4 = (float4*)Xs;
        for (int j = t; j < 256; j += 256) Xs4[j] = Xg4[j];
    }
    __syncthreads();

    float cth[32], sth[32];
#pragma unroll
    for (int k = 0; k < 32; k++) { cth[k] = g_ch[k*256 + t]; sth[k] = g_sh[k*256 + t]; }

    const float scale = 1.0f / 65536.0f;
#pragma unroll 2
    for (int ky = 0; ky < 16; ky++) {
        float re = 0.f, im = 0.f;
#pragma unroll
        for (int k = 0; k < 32; k++) {
            float2 X = Xs[ky*32 + k];
            re = fmaf(X.x, cth[k], fmaf(-X.y, sth[k], re));
            im = fmaf(X.x, sth[k], fmaf( X.y, cth[k], im));
        }
        g_Z[((size_t)bo*256 + t)*16 + ky] = make_float2(re*scale, im*scale);
    }
}

// ---------------- fused: irfft combine over W + 1x1 conv + bias (+GELU), FMA2 ----------------
// Dynamic smem layout (floats): pws[4096] | cst[8*256*4] | Zs[2048] | pbs[64]
#define KF_SMEM_FLOATS (4096 + 8192 + 2048 + 64)
__global__ __launch_bounds__(256, 2) void k_final(int srcsel,
                                                  const float* __restrict__ pw_w,
                                                  const float* __restrict__ pw_b,
                                                  int layer, int apply_gelu) {
    const float* __restrict__ hin  = srcsel ? g_h1 : g_h0;
    float*       __restrict__ hout = srcsel ? g_h0 : g_h1;

    extern __shared__ float smem[];
    float*  pws  = smem;                          // [o][i] 16 KB
    float4* cstf = (float4*)(smem + 4096);        // [q][t] packed (c,-s,c,-s) 32 KB
    float2* Zs   = (float2*)(smem + 4096 + 8192); // [o][ky] 8 KB
    float*  pbs  = smem + 4096 + 8192 + 2048;     // [64]

    int t = threadIdx.x;                          // w
    int bp = blockIdx.x;                          // b*256 + p (4096 blocks)
    int b = bp >> 8, p = bp & 255;

    const float* pwg = pw_w + (size_t)layer * 4096;
    for (int j = t; j < 4096; j += 256) pws[j] = pwg[j];
    if (t < 64) pbs[t] = pw_b[layer*64 + t];
#pragma unroll
    for (int q = 0; q < 8; q++) {                 // packed twiddles per (ky-pair, t)
        float c0 = g_cw[(2*q  )*256 + t], s0 = g_sw[(2*q  )*256 + t];
        float c1 = g_cw[(2*q+1)*256 + t], s1 = g_sw[(2*q+1)*256 + t];
        cstf[q*256 + t] = make_float4(c0, -s0, c1, -s1);
    }
    for (int j = t; j < 1024; j += 256) {         // j = o*16 + ky
        int o = j >> 4, ky = j & 15;
        float2 z = g_Z[((size_t)(b*64 + o)*256 + p)*16 + ky];
        float a = (ky == 0) ? 1.f : 2.f;
        Zs[j] = make_float2(a*z.x, a*z.y);
    }
    __syncthreads();

    const ulonglong2* ee2 = (const ulonglong2*)cstf;   // [q*256 + t]

    // packed input pairs (hv[2q], hv[2q+1])
    size_t pixbase = (size_t)b * NWID * NPIX + (size_t)p * 256 + t;
    ull hv2[32];
#pragma unroll
    for (int q = 0; q < 32; q++) {
        float x0 = hin[pixbase + (size_t)(2*q    ) * NPIX];
        float x1 = hin[pixbase + (size_t)(2*q + 1) * NPIX];
        hv2[q] = pk2(x0, x1);
    }

#pragma unroll 2
    for (int o = 0; o < 64; o++) {
        const ulonglong2* w2 = (const ulonglong2*)(pws + o*64);
        ull a0 = 0ULL, a1 = 0ULL;
#pragma unroll
        for (int q = 0; q < 16; q++) {
            ulonglong2 ww = w2[q];
            a0 = ffma2(hv2[2*q],   ww.x, a0);
            a1 = ffma2(hv2[2*q+1], ww.y, a1);
        }
        const ulonglong2* z2 = (const ulonglong2*)(Zs + o*16);
        ull sp0 = 0ULL, sp1 = 0ULL;
#pragma unroll
        for (int q = 0; q < 8; q++) {
            ulonglong2 zz = z2[q];
            ulonglong2 ee = ee2[q*256 + t];
            sp0 = ffma2(zz.x, ee.x, sp0);
            sp1 = ffma2(zz.y, ee.y, sp1);
        }
        float2 u = up2(add2(add2(a0, a1), add2(sp0, sp1)));
        float val = u.x + u.y + pbs[o];
        if (apply_gelu) val = 0.5f * val * (1.f + erff(val * 0.70710678118654752f));
        hout[pixbase + (size_t)o * NPIX] = val;
    }
}

// ---------------- fused projection: fc1 (64->128) + GELU + fc2 (128->20), FMA2 ----------------
__global__ __launch_bounds__(256, 2) void k_fc12(float* __restrict__ out,
                                                 const float* __restrict__ fc1w, const float* __restrict__ fc1b,
                                                 const float* __restrict__ fc2w, const float* __restrict__ fc2b) {
    __shared__ float w1s[FCH*NWID];               // [j][i] 32 KB
    __shared__ float w2t[FCH*NCOUT];              // [j][k] 10 KB (transposed), 80B rows
    __shared__ float b1s[FCH];
    __shared__ float b2s[NCOUT];
    int t = threadIdx.x;
    for (int j = t; j < FCH*NWID;  j += 256) w1s[j] = fc1w[j];
    for (int j = t; j < NCOUT*FCH; j += 256) {
        int k = j / FCH, jj = j % FCH;
        w2t[jj*NCOUT + k] = fc2w[j];
    }
    if (t < FCH)   b1s[t] = fc1b[t];
    if (t < NCOUT) b2s[t] = fc2b[t];
    __syncthreads();

    int bp = blockIdx.x;                          // b*256 + p (4096 blocks)
    int b = bp >> 8, p = bp & 255;
    size_t pixbase = (size_t)b * NWID * NPIX + (size_t)p * 256 + t;

    ull hv2[32];
#pragma unroll
    for (int q = 0; q < 32; q++) {
        float x0 = g_h0[pixbase + (size_t)(2*q    ) * NPIX];
        float x1 = g_h0[pixbase + (size_t)(2*q + 1) * NPIX];
        hv2[q] = pk2(x0, x1);
    }

    ull acc2[10];
#pragma unroll
    for (int q = 0; q < 10; q++) acc2[q] = pk2(b2s[2*q], b2s[2*q+1]);

    for (int j = 0; j < FCH; j++) {
        const ulonglong2* w2 = (const ulonglong2*)(w1s + j*NWID);
        ull a0 = 0ULL, a1 = 0ULL;
#pragma unroll
        for (int q = 0; q < 16; q++) {
            ulonglong2 ww = w2[q];
            a0 = ffma2(hv2[2*q],   ww.x, a0);
            a1 = ffma2(hv2[2*q+1], ww.y, a1);
        }
        float2 u = up2(add2(a0, a1));
        float s = u.x + u.y + b1s[j];
        s = 0.5f * s * (1.f + erff(s * 0.70710678118654752f));
        ull ss = pk2(s, s);
        const ulonglong2* v2 = (const ulonglong2*)(w2t + j*NCOUT);  // 20 floats = 5 x 16B
#pragma unroll
        for (int q = 0; q < 5; q++) {
            ulonglong2 ww = v2[q];
            acc2[2*q]   = ffma2(ss, ww.x, acc2[2*q]);
            acc2[2*q+1] = ffma2(ss, ww.y, acc2[2*q+1]);
        }
    }
#pragma unroll
    for (int q = 0; q < 10; q++) {
        float2 u = up2(acc2[q]);
        out[(size_t)(b*NCOUT + 2*q    )*NPIX + (size_t)p*256 + t] = u.x;
        out[(size_t)(b*NCOUT + 2*q + 1)*NPIX + (size_t)p*256 + t] = u.y;
    }
}

// ---------------- launch ----------------
extern "C" void kernel_launch(void* const* d_in, const int* in_sizes, int n_in,
                              void* d_out, int out_size) {
    const float* x    = (const float*)d_in[0];
    const float* w1r  = (const float*)d_in[1];
    const float* w1i  = (const float*)d_in[2];
    const float* w2r  = (const float*)d_in[3];
    const float* w2i  = (const float*)d_in[4];
    const float* pw_w = (const float*)d_in[5];
    const float* pw_b = (const float*)d_in[6];
    const float* fc0w = (const float*)d_in[7];
    const float* fc0b = (const float*)d_in[8];
    const float* fc1w = (const float*)d_in[9];
    const float* fc1b = (const float*)d_in[10];
    const float* fc2w = (const float*)d_in[11];
    const float* fc2b = (const float*)d_in[12];
    float* out = (float*)d_out;

    const int kf_smem = KF_SMEM_FLOATS * 4;       // 57,600 B dynamic smem
    cudaFuncSetAttribute(k_final, cudaFuncAttributeMaxDynamicSharedMemorySize, kf_smem);

    k_init_tables<<<32, 256>>>();
    k_fc0<<<4096, 256>>>(x, fc0w, fc0b);

    for (int l = 0; l < NLAY; l++) {
        int src = l & 1;                          // 0: read g_h0/write g_h1, 1: reverse
        k_dftw<<<16384, 256>>>(src);
        k_dfth<<<1024, 256>>>();
        k_modemix<<<512, 256>>>(w1r, w1i, w2r, w2i, l);
        k_idfth<<<1024, 256>>>();
        k_final<<<4096, 256, kf_smem>>>(src, pw_w, pw_b, l, (l < 3) ? 1 : 0);
    }
    // after l=3 (src=1), result lives in g_h0
    k_fc12<<<4096, 256>>>(out, fc1w, fc1b, fc2w, fc2b);
}

// round 10
// speedup vs baseline: 1.5016x; 1.5016x over previous
#include <cuda_runtime.h>
#include <math.h>

// ---------------- problem constants ----------------
#define NB    16
#define NCIN  20
#define NWID  64
#define NPIX  65536      // 256*256
#define NLAY  4
#define M1    16
#define M2    16
#define FCH   128
#define NCOUT 20

typedef unsigned long long ull;
typedef unsigned int uint;

// ---- packed f32x2 helpers ----
__device__ __forceinline__ ull ffma2(ull a, ull b, ull c) {
    ull d; asm("fma.rn.f32x2 %0, %1, %2, %3;" : "=l"(d) : "l"(a), "l"(b), "l"(c)); return d;
}
__device__ __forceinline__ ull add2(ull a, ull b) {
    ull d; asm("add.rn.f32x2 %0, %1, %2;" : "=l"(d) : "l"(a), "l"(b)); return d;
}
__device__ __forceinline__ ull pk2(float lo, float hi) {
    ull r; asm("mov.b64 %0, {%1,%2};" : "=l"(r) : "f"(lo), "f"(hi)); return r;
}
__device__ __forceinline__ float2 up2(ull v) {
    float2 r; asm("mov.b64 {%0,%1}, %2;" : "=f"(r.x), "=f"(r.y) : "l"(v)); return r;
}

// ---- tf32 mma helpers ----
__device__ __forceinline__ uint tf32u(float x) {
    uint y; asm("cvt.rna.tf32.f32 %0, %1;" : "=r"(y) : "f"(x)); return y;
}
#define MMA_TF32(d, a, b) \
    asm volatile("mma.sync.aligned.m16n8k8.row.col.f32.tf32.tf32.f32 " \
                 "{%0,%1,%2,%3}, {%4,%5,%6,%7}, {%8,%9}, {%0,%1,%2,%3};" \
                 : "+f"((d)[0]), "+f"((d)[1]), "+f"((d)[2]), "+f"((d)[3]) \
                 : "r"((a)[0]), "r"((a)[1]), "r"((a)[2]), "r"((a)[3]), \
                   "r"((b)[0]), "r"((b)[1]))

__device__ __forceinline__ float gelu_f(float v) {
    return 0.5f * v * (1.f + erff(v * 0.70710678118654752f));
}

// ---------------- device scratch (no allocations allowed) ----------------
__device__ float  g_h0[NB*NWID*NPIX];          // 256 MB ping
__device__ float  g_h1[NB*NWID*NPIX];          // 256 MB pong
__device__ float2 g_T  [NB*NWID*16*256];       // fwd stage1: [b][i][ky][h]
__device__ float2 g_Xf [32*16*NB*NWID];        // fwd modes:  [kx][ky][b][i]
__device__ float2 g_Xo [NB*NWID*16*32];        // mixed:      [b][o][ky][kx]
__device__ float2 g_Z  [NB*NWID*256*16];       // inv stage1: [b][o][p][ky]
// twiddle tables
__device__ float g_cw[16*256], g_sw[16*256];   // cos/sin(2*pi*ky*w/256)  [ky][w]
__device__ float g_ch[32*256], g_sh[32*256];   // cos/sin(2*pi*kx*h/256)  [k][h]
__device__ float g_chT[256*32], g_shT[256*32]; // transposed [h][k]
__device__ float g_E[32*128];                  // packed DFT-W twiddles

// ---------------- table init ----------------
__global__ __launch_bounds__(256) void k_init_tables() {
    int id = blockIdx.x * 256 + threadIdx.x;
    if (id < 16*256) {
        int ky = id >> 8, w = id & 255;
        float s, c;
        sincospif((float)(ky * w) * (1.0f/128.0f), &s, &c);
        g_cw[id] = c; g_sw[id] = s;
    }
    if (id < 32*256) {
        int k = id >> 8, h = id & 255;
        int kx = (k < 16) ? k : (224 + k);
        float s, c;
        sincospif((float)(kx * h) * (1.0f/128.0f), &s, &c);
        g_ch[id] = c;        g_sh[id] = s;
        g_chT[h*32 + k] = c; g_shT[h*32 + k] = s;
    }
    if (id < 32*128) {
        int c = id >> 7, w = id & 127;
        int ky = (c < 16) ? ((c >> 1) << 1) : (((((c - 16) >> 1)) << 1) + 1);
        int comp = c & 1;
        float s, cv;
        sincospif((float)(ky * w) * (1.0f/128.0f), &s, &cv);
        g_E[id] = comp ? -s : cv;
    }
}

// ---------------- lift: h0[b,d,pix] ----------------
__global__ __launch_bounds__(256) void k_fc0(const float* __restrict__ x,
                                             const float* __restrict__ w,
                                             const float* __restrict__ bias) {
    __shared__ float ws[NWID*NCIN];
    __shared__ float bs[NWID];
    int t = threadIdx.x;
    for (int j = t; j < NWID*NCIN; j += 256) ws[j] = w[j];
    if (t < NWID) bs[t] = bias[t];
    __syncthreads();

    int idx = blockIdx.x * 256 + t;
    int b = idx >> 16, pix = idx & 65535;
    ull xin2[10];
#pragma unroll
    for (int q = 0; q < 10; q++) {
        float x0 = x[(size_t)(b*NCIN + 2*q    )*NPIX + pix];
        float x1 = x[(size_t)(b*NCIN + 2*q + 1)*NPIX + pix];
        xin2[q] = pk2(x0, x1);
    }
#pragma unroll 4
    for (int d = 0; d < NWID; d++) {
        const ulonglong2* wp = (const ulonglong2*)(ws + d*NCIN);
        ull a0 = 0ULL, a1 = 0ULL;
#pragma unroll
        for (int q = 0; q < 5; q++) {
            ulonglong2 ww = wp[q];
            a0 = ffma2(xin2[2*q],   ww.x, a0);
            a1 = ffma2(xin2[2*q+1], ww.y, a1);
        }
        float2 u = up2(add2(a0, a1));
        g_h0[(size_t)(b*NWID + d)*NPIX + pix] = u.x + u.y + bs[d];
    }
}

// ---------------- forward DFT over W (radix-2 fold + FMA2 GEMM) ----------------
__global__ __launch_bounds__(256) void k_dftw(int srcsel) {
    const float* __restrict__ hin = srcsel ? g_h1 : g_h0;
    __shared__ float Fs[16*276];
    __shared__ float Es[32*136];
    int t = threadIdx.x;
    int lane = t & 31, warp = t >> 5;

    if (warp < 4) {
#pragma unroll
        for (int k = 0; k < 4; k++) {
            int r = warp * 4 + k;
            const float4* src4 = (const float4*)(hin + ((size_t)blockIdx.x * 16 + r) * 256);
            float4 lo = src4[lane], hi = src4[lane + 32];
            float4 A = make_float4(lo.x+hi.x, lo.y+hi.y, lo.z+hi.z, lo.w+hi.w);
            float4 B = make_float4(lo.x-hi.x, lo.y-hi.y, lo.z-hi.z, lo.w-hi.w);
            *(float4*)(Fs + r*276 +       lane*4) = A;
            *(float4*)(Fs + r*276 + 144 + lane*4) = B;
        }
    } else {
        int t2 = t - 128;
        for (int j = t2; j < 4096; j += 128) {
            int c = j >> 7, w = j & 127;
            Es[c*136 + (w >> 6)*68 + (w & 63)] = g_E[j];
        }
    }
    __syncthreads();

    int rloc  = lane & 15;
    int whalf = lane >> 4;
    const float* vbase = Fs + rloc*276 + ((warp >= 4) ? 144 : 0) + whalf*64;
    const float* ebase = Es + (warp*4)*136 + whalf*68;

    ull acc[8];
#pragma unroll
    for (int q = 0; q < 8; q++) acc[q] = 0ULL;

#pragma unroll
    for (int it = 0; it < 16; it++) {
        int wl = it * 4;
        ulonglong2 v = *(const ulonglong2*)(vbase + wl);
#pragma unroll
        for (int c = 0; c < 4; c++) {
            ulonglong2 e = *(const ulonglong2*)(ebase + c*136 + wl);
            acc[2*c]   = ffma2(v.x, e.x, acc[2*c]);
            acc[2*c+1] = ffma2(v.y, e.y, acc[2*c+1]);
        }
    }

    float s[4];
#pragma unroll
    for (int c = 0; c < 4; c++) {
        float2 u = up2(add2(acc[2*c], acc[2*c+1]));
        float v = u.x + u.y;
        v += __shfl_xor_sync(0xffffffffu, v, 16);
        s[c] = v;
    }
    if (whalf == 0) {
        int bi = blockIdx.x >> 4;
        int h  = (blockIdx.x & 15) * 16 + rloc;
        int kyA = (warp < 4) ? 4*warp : 4*(warp - 4) + 1;
        g_T[(size_t)bi*4096 + (kyA    )*256 + h] = make_float2(s[0], s[1]);
        g_T[(size_t)bi*4096 + (kyA + 2)*256 + h] = make_float2(s[2], s[3]);
    }
}

// ---------------- forward DFT over H (rotation recurrence) ----------------
__global__ __launch_bounds__(256) void k_dfth() {
    __shared__ float2 Ts[16*256];
    int bi = blockIdx.x;
    int t = threadIdx.x;
    {
        const float4* Tg4 = (const float4*)(g_T + (size_t)bi * 4096);
        float4* Ts4 = (float4*)Ts;
        for (int j = t; j < 2048; j += 256) Ts4[j] = Tg4[j];
    }
    __syncthreads();

    int kx  = t & 31;
    int ky  = t >> 5;
    int b = bi >> 6, i = bi & 63;

    float c0 = g_chT[32 + kx], s0 = g_shT[32 + kx];
    float c = 1.f, s = 0.f;
    float re0 = 0.f, im0 = 0.f, re1 = 0.f, im1 = 0.f;
#pragma unroll 4
    for (int h = 0; h < 256; h++) {
        float2 a  = Ts[ky*256 + h];
        float2 bq = Ts[(ky + 8)*256 + h];
        re0 = fmaf(a.x,  c, fmaf( a.y,  s, re0));
        im0 = fmaf(a.y,  c, fmaf(-a.x,  s, im0));
        re1 = fmaf(bq.x, c, fmaf( bq.y, s, re1));
        im1 = fmaf(bq.y, c, fmaf(-bq.x, s, im1));
        float cn = fmaf(-s, s0, c*c0);
        float sn = fmaf( c, s0, s*c0);
        c = cn; s = sn;
    }
    g_Xf[((size_t)(kx*16 + ky    )*16 + b)*64 + i] = make_float2(re0, im0);
    g_Xf[((size_t)(kx*16 + ky + 8)*16 + b)*64 + i] = make_float2(re1, im1);
}

// ---------------- per-mode complex GEMM ----------------
__global__ __launch_bounds__(256) void k_modemix(const float* __restrict__ w1r, const float* __restrict__ w1i,
                                                 const float* __restrict__ w2r, const float* __restrict__ w2i,
                                                 int layer) {
    __shared__ float2 Xs[16*64];
    __shared__ float2 Ws[64*64];
    int mode = blockIdx.x;
    int kx = mode >> 4, ky = mode & 15;
    int t = threadIdx.x;

    const float2* Xg = g_Xf + (size_t)mode * 1024;
    for (int j = t; j < 1024; j += 256) Xs[j] = Xg[j];

    const float* wr; const float* wi; int kxp;
    if (kx < 16) { wr = w1r; wi = w1i; kxp = kx; }
    else         { wr = w2r; wi = w2i; kxp = kx - 16; }
    size_t base = (size_t)layer * (NWID*NWID*256) + (size_t)kxp*16 + ky;
    for (int j = t; j < 4096; j += 256) {
        Ws[j] = make_float2(wr[base + (size_t)j*256], wi[base + (size_t)j*256]);
    }
    __syncthreads();

#pragma unroll
    for (int r = 0; r < 4; r++) {
        int oid = t + 256*r;
        int b = oid >> 6, o = oid & 63;
        float re = 0.f, im = 0.f;
#pragma unroll 8
        for (int i = 0; i < 64; i++) {
            float2 X = Xs[b*64 + i];
            float2 W = Ws[i*64 + o];
            re = fmaf(X.x, W.x, fmaf(-X.y, W.y, re));
            im = fmaf(X.x, W.y, fmaf( X.y, W.x, im));
        }
        g_Xo[((size_t)(b*64 + o)*16 + ky)*32 + kx] = make_float2(re, im);
    }
}

// ---------------- inverse DFT over H ----------------
__global__ __launch_bounds__(256) void k_idfth() {
    __shared__ float2 Xs[16*32];
    int bo = blockIdx.x;
    int t = threadIdx.x;
    {
        const float4* Xg4 = (const float4*)(g_Xo + (size_t)bo * 512);
        float4* Xs4 = (float4*)Xs;
        for (int j = t; j < 256; j += 256) Xs4[j] = Xg4[j];
    }
    __syncthreads();

    float cth[32], sth[32];
#pragma unroll
    for (int k = 0; k < 32; k++) { cth[k] = g_ch[k*256 + t]; sth[k] = g_sh[k*256 + t]; }

    const float scale = 1.0f / 65536.0f;
#pragma unroll 2
    for (int ky = 0; ky < 16; ky++) {
        float re = 0.f, im = 0.f;
#pragma unroll
        for (int k = 0; k < 32; k++) {
            float2 X = Xs[ky*32 + k];
            re = fmaf(X.x, cth[k], fmaf(-X.y, sth[k], re));
            im = fmaf(X.x, sth[k], fmaf( X.y, cth[k], im));
        }
        g_Z[((size_t)bo*256 + t)*16 + ky] = make_float2(re*scale, im*scale);
    }
}

// ---------------- k_final as tf32 MMA GEMM ----------------
// Per block: one (b, p, half): out[w(128), o(64)] = A[w][k(96)] x B[k][o]
//   A = [hin rows 0..63 | E twiddles 64..95], B = [pw_w ; a*Z]
// smem (uints/floats): As[96][136] k-major, Bs[96][72] k-major, pbs[64]
#define KF_SMEM_BYTES ((96*136 + 96*72 + 64) * 4)
__global__ __launch_bounds__(256) void k_final(int srcsel,
                                               const float* __restrict__ pw_w,
                                               const float* __restrict__ pw_b,
                                               int layer, int apply_gelu) {
    const float* __restrict__ hin  = srcsel ? g_h1 : g_h0;
    float*       __restrict__ hout = srcsel ? g_h0 : g_h1;

    extern __shared__ uint smem_u[];
    uint*  As  = smem_u;                       // [k][w] stride 136
    uint*  Bs  = smem_u + 96*136;              // [k][o] stride 72
    float* pbs = (float*)(smem_u + 96*136 + 96*72);

    int t = threadIdx.x;
    int lane = t & 31, warp = t >> 5;
    int bx = blockIdx.x;                       // 8192 = b(16) * p(256) * half(2)
    int b = bx >> 9, p = (bx >> 1) & 255, half = bx & 1;
    int w0 = half * 128;

    // --- load A conv rows (k = i < 64): As[i][w] = tf32(hin[b,i,p,w0+w])
    const float* hsrc = hin + (size_t)(b*64)*NPIX + (size_t)p*256 + w0;
#pragma unroll
    for (int rr = 0; rr < 8; rr++) {
        int i = warp*8 + rr;
        float4 v = *(const float4*)(hsrc + (size_t)i*NPIX + lane*4);
        uint4 uv = make_uint4(tf32u(v.x), tf32u(v.y), tf32u(v.z), tf32u(v.w));
        *(uint4*)(As + i*136 + lane*4) = uv;
    }
    // --- A spectral rows (k = 64+e): e=2q -> cw, e=2q+1 -> -sw
#pragma unroll
    for (int rep = 0; rep < 16; rep++) {
        int j = rep*256 + t;                   // 4096 = e(32) * w(128)
        int e = j >> 7, w = j & 127;
        int q = e >> 1;
        float v = (e & 1) ? -g_sw[q*256 + w0 + w] : g_cw[q*256 + w0 + w];
        As[(64 + e)*136 + w] = tf32u(v);
    }
    // --- B conv rows: Bs[i][o] = tf32(pw_w[layer][o][i])
    const float* pwg = pw_w + (size_t)layer * 4096;
#pragma unroll
    for (int rep = 0; rep < 16; rep++) {
        int j = rep*256 + t;                   // 4096 = o*64 + i
        int o = j >> 6, i = j & 63;
        Bs[i*72 + o] = tf32u(pwg[j]);
    }
    // --- B spectral rows: Bs[64+2q][o] = a*Zr, Bs[64+2q+1][o] = a*Zi
#pragma unroll
    for (int rep = 0; rep < 4; rep++) {
        int j = rep*256 + t;                   // 1024 = o*16 + q
        int o = j >> 4, q = j & 15;
        float2 z = g_Z[((size_t)(b*64 + o)*256 + p)*16 + q];
        float a = q ? 2.f : 1.f;
        Bs[(64 + 2*q    )*72 + o] = tf32u(a * z.x);
        Bs[(64 + 2*q + 1)*72 + o] = tf32u(a * z.y);
    }
    if (t < 64) pbs[t] = pw_b[layer*64 + t];
    __syncthreads();

    // --- mma: warp grid 4M x 2N; each warp 32 rows x 32 cols
    int warpM = warp & 3, warpN = warp >> 2;
    int m0 = warpM * 32, n0 = warpN * 32;
    int gr = lane >> 2, gc = lane & 3;

    float acc[2][4][4];
#pragma unroll
    for (int mi = 0; mi < 2; mi++)
#pragma unroll
        for (int ni = 0; ni < 4; ni++)
#pragma unroll
            for (int e = 0; e < 4; e++) acc[mi][ni][e] = 0.f;

#pragma unroll
    for (int ks = 0; ks < 12; ks++) {
        int k0 = ks * 8;
        uint a[2][4];
#pragma unroll
        for (int mi = 0; mi < 2; mi++) {
            int r = m0 + mi*16 + gr;
            a[mi][0] = As[(k0 + gc    )*136 + r];
            a[mi][1] = As[(k0 + gc    )*136 + r + 8];
            a[mi][2] = As[(k0 + gc + 4)*136 + r];
            a[mi][3] = As[(k0 + gc + 4)*136 + r + 8];
        }
        uint bf[4][2];
#pragma unroll
        for (int ni = 0; ni < 4; ni++) {
            int n = n0 + ni*8 + gr;
            bf[ni][0] = Bs[(k0 + gc    )*72 + n];
            bf[ni][1] = Bs[(k0 + gc + 4)*72 + n];
        }
#pragma unroll
        for (int mi = 0; mi < 2; mi++)
#pragma unroll
            for (int ni = 0; ni < 4; ni++)
                MMA_TF32(acc[mi][ni], a[mi], bf[ni]);
    }

    // --- epilogue
    size_t outbase = (size_t)(b*64)*NPIX + (size_t)p*256 + w0;
#pragma unroll
    for (int mi = 0; mi < 2; mi++)
#pragma unroll
        for (int ni = 0; ni < 4; ni++)
#pragma unroll
            for (int e = 0; e < 4; e++) {
                int row = m0 + mi*16 + gr + (e >> 1)*8;
                int col = n0 + ni*8 + 2*gc + (e & 1);
                float val = acc[mi][ni][e] + pbs[col];
                if (apply_gelu) val = gelu_f(val);
                hout[outbase + (size_t)col*NPIX + row] = val;
            }
}

// ---------------- fc1+GELU+fc2 as tf32 MMA ----------------
// GEMM1: [128 x 64] x [64 x 128] -> gelu -> Hs ; GEMM2: [128 x 128] x [128 x 24(pad)]
// smem union: As[64][136] + Bs1[64][136]  (= Hs[128][136])  |  Bs2[128][40] | b1s[128] | b2s[32]
#define KFC_SMEM_BYTES ((128*136 + 128*40 + 128 + 32) * 4)
__global__ __launch_bounds__(256) void k_fc12(float* __restrict__ out,
                                              const float* __restrict__ fc1w, const float* __restrict__ fc1b,
                                              const float* __restrict__ fc2w, const float* __restrict__ fc2b) {
    extern __shared__ uint smem_u[];
    uint*  As  = smem_u;                        // [i][w] stride 136 (k-major)
    uint*  Bs1 = smem_u + 64*136;               // [i][j] stride 136
    uint*  Hs  = smem_u;                        // [j][w] stride 136 (overlaps As+Bs1)
    uint*  Bs2 = smem_u + 128*136;              // [j][o] stride 40
    float* b1s = (float*)(smem_u + 128*136 + 128*40);
    float* b2s = b1s + 128;

    int t = threadIdx.x;
    int lane = t & 31, warp = t >> 5;
    int bx = blockIdx.x;
    int b = bx >> 9, p = (bx >> 1) & 255, half = bx & 1;
    int w0 = half * 128;

    // --- load A (h) rows
    const float* hsrc = g_h0 + (size_t)(b*64)*NPIX + (size_t)p*256 + w0;
#pragma unroll
    for (int rr = 0; rr < 8; rr++) {
        int i = warp*8 + rr;
        float4 v = *(const float4*)(hsrc + (size_t)i*NPIX + lane*4);
        uint4 uv = make_uint4(tf32u(v.x), tf32u(v.y), tf32u(v.z), tf32u(v.w));
        *(uint4*)(As + i*136 + lane*4) = uv;
    }
    // --- B1: Bs1[i][j] = tf32(fc1w[j][i])
#pragma unroll
    for (int rep = 0; rep < 32; rep++) {
        int j2 = rep*256 + t;                  // 8192 = j*64 + i
        int jj = j2 >> 6, i = j2 & 63;
        Bs1[i*136 + jj] = tf32u(fc1w[j2]);
    }
    // --- B2: Bs2[j][o] = tf32(fc2w[o][j]) for o<20, else 0   (3072 = jj*24 + o)
#pragma unroll
    for (int rep = 0; rep < 12; rep++) {
        int j2 = rep*256 + t;
        int jj = j2 / 24, o = j2 - jj*24;
        float v = (o < 20) ? fc2w[o*FCH + jj] : 0.f;
        Bs2[jj*40 + o] = tf32u(v);
    }
    if (t < FCH)   b1s[t] = fc1b[t];
    if (t < NCOUT) b2s[t] = fc2b[t];
    __syncthreads();

    int gr = lane >> 2, gc = lane & 3;

    // --- GEMM1: warp grid 2M x 4N; warp = 64 rows x 32 cols
    int warpM = warp & 1, warpN = warp >> 1;
    int m0 = warpM * 64, n0 = warpN * 32;
    float acc1[4][4][4];
#pragma unroll
    for (int mi = 0; mi < 4; mi++)
#pragma unroll
        for (int ni = 0; ni < 4; ni++)
#pragma unroll
            for (int e = 0; e < 4; e++) acc1[mi][ni][e] = 0.f;

#pragma unroll
    for (int ks = 0; ks < 8; ks++) {
        int k0 = ks * 8;
        uint a[4][4];
#pragma unroll
        for (int mi = 0; mi < 4; mi++) {
            int r = m0 + mi*16 + gr;
            a[mi][0] = As[(k0 + gc    )*136 + r];
            a[mi][1] = As[(k0 + gc    )*136 + r + 8];
            a[mi][2] = As[(k0 + gc + 4)*136 + r];
            a[mi][3] = As[(k0 + gc + 4)*136 + r + 8];
        }
        uint bf[4][2];
#pragma unroll
        for (int ni = 0; ni < 4; ni++) {
            int n = n0 + ni*8 + gr;
            bf[ni][0] = Bs1[(k0 + gc    )*136 + n];
            bf[ni][1] = Bs1[(k0 + gc + 4)*136 + n];
        }
#pragma unroll
        for (int mi = 0; mi < 4; mi++)
#pragma unroll
            for (int ni = 0; ni < 4; ni++)
                MMA_TF32(acc1[mi][ni], a[mi], bf[ni]);
    }

    __syncthreads();   // everyone done reading As/Bs1; safe to overwrite with Hs

    // --- bias + GELU -> Hs[j][w] (k-major for GEMM2)
#pragma unroll
    for (int mi = 0; mi < 4; mi++)
#pragma unroll
        for (int ni = 0; ni < 4; ni++)
#pragma unroll
            for (int e = 0; e < 4; e++) {
                int row = m0 + mi*16 + gr + (e >> 1)*8;
                int col = n0 + ni*8 + 2*gc + (e & 1);
                float v = gelu_f(acc1[mi][ni][e] + b1s[col]);
                Hs[col*136 + row] = tf32u(v);
            }
    __syncthreads();

    // --- GEMM2: warp = 1 m-tile (16 rows), 3 n-tiles (24 cols)
    int m0b = warp * 16;
    float acc2[3][4];
#pragma unroll
    for (int ni = 0; ni < 3; ni++)
#pragma unroll
        for (int e = 0; e < 4; e++) acc2[ni][e] = 0.f;

#pragma unroll
    for (int ks = 0; ks < 16; ks++) {
        int k0 = ks * 8;
        uint a[4];
        {
            int r = m0b + gr;
            a[0] = Hs[(k0 + gc    )*136 + r];
            a[1] = Hs[(k0 + gc    )*136 + r + 8];
            a[2] = Hs[(k0 + gc + 4)*136 + r];
            a[3] = Hs[(k0 + gc + 4)*136 + r + 8];
        }
        uint bf[3][2];
#pragma unroll
        for (int ni = 0; ni < 3; ni++) {
            int n = ni*8 + gr;
            bf[ni][0] = Bs2[(k0 + gc    )*40 + n];
            bf[ni][1] = Bs2[(k0 + gc + 4)*40 + n];
        }
#pragma unroll
        for (int ni = 0; ni < 3; ni++)
            MMA_TF32(acc2[ni], a, bf[ni]);
    }

    // --- epilogue
    size_t outbase = (size_t)(b*NCOUT)*NPIX + (size_t)p*256 + w0;
#pragma unroll
    for (int ni = 0; ni < 3; ni++)
#pragma unroll
        for (int e = 0; e < 4; e++) {
            int row = m0b + gr + (e >> 1)*8;
            int col = ni*8 + 2*gc + (e & 1);
            if (col < NCOUT)
                out[outbase + (size_t)col*NPIX + row] = acc2[ni][e] + b2s[col];
        }
}

// ---------------- launch ----------------
extern "C" void kernel_launch(void* const* d_in, const int* in_sizes, int n_in,
                              void* d_out, int out_size) {
    const float* x    = (const float*)d_in[0];
    const float* w1r  = (const float*)d_in[1];
    const float* w1i  = (const float*)d_in[2];
    const float* w2r  = (const float*)d_in[3];
    const float* w2i  = (const float*)d_in[4];
    const float* pw_w = (const float*)d_in[5];
    const float* pw_b = (const float*)d_in[6];
    const float* fc0w = (const float*)d_in[7];
    const float* fc0b = (const float*)d_in[8];
    const float* fc1w = (const float*)d_in[9];
    const float* fc1b = (const float*)d_in[10];
    const float* fc2w = (const float*)d_in[11];
    const float* fc2b = (const float*)d_in[12];
    float* out = (float*)d_out;

    cudaFuncSetAttribute(k_final, cudaFuncAttributeMaxDynamicSharedMemorySize, KF_SMEM_BYTES);
    cudaFuncSetAttribute(k_fc12,  cudaFuncAttributeMaxDynamicSharedMemorySize, KFC_SMEM_BYTES);

    k_init_tables<<<32, 256>>>();
    k_fc0<<<4096, 256>>>(x, fc0w, fc0b);

    for (int l = 0; l < NLAY; l++) {
        int src = l & 1;
        k_dftw<<<16384, 256>>>(src);
        k_dfth<<<1024, 256>>>();
        k_modemix<<<512, 256>>>(w1r, w1i, w2r, w2i, l);
        k_idfth<<<1024, 256>>>();
        k_final<<<8192, 256, KF_SMEM_BYTES>>>(src, pw_w, pw_b, l, (l < 3) ? 1 : 0);
    }
    // after l=3 (src=1), result lives in g_h0
    k_fc12<<<8192, 256, KFC_SMEM_BYTES>>>(out, fc1w, fc1b, fc2w, fc2b);
}

// round 11
// speedup vs baseline: 1.6116x; 1.0732x over previous
#include <cuda_runtime.h>
#include <math.h>

// ---------------- problem constants ----------------
#define NB    16
#define NCIN  20
#define NWID  64
#define NPIX  65536      // 256*256
#define NLAY  4
#define M1    16
#define M2    16
#define FCH   128
#define NCOUT 20

typedef unsigned long long ull;
typedef unsigned int uint;

// ---- packed f32x2 helpers ----
__device__ __forceinline__ ull ffma2(ull a, ull b, ull c) {
    ull d; asm("fma.rn.f32x2 %0, %1, %2, %3;" : "=l"(d) : "l"(a), "l"(b), "l"(c)); return d;
}
__device__ __forceinline__ ull add2(ull a, ull b) {
    ull d; asm("add.rn.f32x2 %0, %1, %2;" : "=l"(d) : "l"(a), "l"(b)); return d;
}
__device__ __forceinline__ ull pk2(float lo, float hi) {
    ull r; asm("mov.b64 %0, {%1,%2};" : "=l"(r) : "f"(lo), "f"(hi)); return r;
}
__device__ __forceinline__ float2 up2(ull v) {
    float2 r; asm("mov.b64 {%0,%1}, %2;" : "=f"(r.x), "=f"(r.y) : "l"(v)); return r;
}

// ---- tf32 mma helpers ----
__device__ __forceinline__ uint tf32u(float x) {
    uint y; asm("cvt.rna.tf32.f32 %0, %1;" : "=r"(y) : "f"(x)); return y;
}
#define MMA_TF32(d, a, b) \
    asm volatile("mma.sync.aligned.m16n8k8.row.col.f32.tf32.tf32.f32 " \
                 "{%0,%1,%2,%3}, {%4,%5,%6,%7}, {%8,%9}, {%0,%1,%2,%3};" \
                 : "+f"((d)[0]), "+f"((d)[1]), "+f"((d)[2]), "+f"((d)[3]) \
                 : "r"((a)[0]), "r"((a)[1]), "r"((a)[2]), "r"((a)[3]), \
                   "r"((b)[0]), "r"((b)[1]))

__device__ __forceinline__ float gelu_f(float v) {
    return 0.5f * v * (1.f + erff(v * 0.70710678118654752f));
}

// ---------------- device scratch (no allocations allowed) ----------------
__device__ float  g_h0[NB*NWID*NPIX];          // 256 MB ping
__device__ float  g_h1[NB*NWID*NPIX];          // 256 MB pong
__device__ float2 g_T  [NB*NWID*16*256];       // fwd stage1: [b][i][ky][h]
__device__ float2 g_Xf [32*16*NB*NWID];        // fwd modes:  [kx][ky][b][i]
__device__ float2 g_Xo [NB*NWID*16*32];        // mixed:      [b][o][ky][kx]
__device__ float2 g_Z  [NB*NWID*256*16];       // inv stage1: [b][o][p][ky]
// twiddle tables
__device__ float g_cw[16*256], g_sw[16*256];   // cos/sin(2*pi*ky*w/256)  [ky][w]
__device__ float g_ch[32*256], g_sh[32*256];   // cos/sin(2*pi*kx*h/256)  [k][h]
__device__ float g_E256[256*32];               // DFT-W B-matrix: [w][2ky]=cos, [2ky+1]=-sin

// ---------------- table init ----------------
__global__ __launch_bounds__(256) void k_init_tables() {
    int id = blockIdx.x * 256 + threadIdx.x;   // 8192 threads
    if (id < 16*256) {
        int ky = id >> 8, w = id & 255;
        float s, c;
        sincospif((float)(ky * w) * (1.0f/128.0f), &s, &c);
        g_cw[id] = c; g_sw[id] = s;
    }
    if (id < 32*256) {
        int k = id >> 8, h = id & 255;
        int kx = (k < 16) ? k : (224 + k);
        float s, c;
        sincospif((float)(kx * h) * (1.0f/128.0f), &s, &c);
        g_ch[id] = c; g_sh[id] = s;
    }
    {   // E256: id covers all 8192 entries
        int w = id >> 5, c = id & 31;
        int ky = c >> 1;
        float s, cv;
        sincospif((float)(ky * w) * (1.0f/128.0f), &s, &cv);
        g_E256[id] = (c & 1) ? -s : cv;
    }
}

// ---------------- lift: h0[b,d,pix] ----------------
__global__ __launch_bounds__(256) void k_fc0(const float* __restrict__ x,
                                             const float* __restrict__ w,
                                             const float* __restrict__ bias) {
    __shared__ float ws[NWID*NCIN];
    __shared__ float bs[NWID];
    int t = threadIdx.x;
    for (int j = t; j < NWID*NCIN; j += 256) ws[j] = w[j];
    if (t < NWID) bs[t] = bias[t];
    __syncthreads();

    int idx = blockIdx.x * 256 + t;
    int b = idx >> 16, pix = idx & 65535;
    ull xin2[10];
#pragma unroll
    for (int q = 0; q < 10; q++) {
        float x0 = x[(size_t)(b*NCIN + 2*q    )*NPIX + pix];
        float x1 = x[(size_t)(b*NCIN + 2*q + 1)*NPIX + pix];
        xin2[q] = pk2(x0, x1);
    }
#pragma unroll 4
    for (int d = 0; d < NWID; d++) {
        const ulonglong2* wp = (const ulonglong2*)(ws + d*NCIN);
        ull a0 = 0ULL, a1 = 0ULL;
#pragma unroll
        for (int q = 0; q < 5; q++) {
            ulonglong2 ww = wp[q];
            a0 = ffma2(xin2[2*q],   ww.x, a0);
            a1 = ffma2(xin2[2*q+1], ww.y, a1);
        }
        float2 u = up2(add2(a0, a1));
        g_h0[(size_t)(b*NWID + d)*NPIX + pix] = u.x + u.y + bs[d];
    }
}

// ---------------- forward DFT over W as tf32 MMA ----------------
// Per block: 64 consecutive (b,i,h)-rows. out[row][32] = A[64x256] x E256[256x32]
#define DFTW_SMEM ((64*260 + 256*40) * 4)
__global__ __launch_bounds__(256) void k_dftw(int srcsel) {
    const float* __restrict__ hin = srcsel ? g_h1 : g_h0;
    extern __shared__ uint sm[];
    uint* As = sm;               // [m=64][k=256] stride 260  (66.5 KB)
    uint* Bs = sm + 64*260;      // [k=256][n=32] stride 40   (41 KB)
    int t = threadIdx.x, lane = t & 31, warp = t >> 5;
    int gr = lane >> 2, gc = lane & 3;

    // load A: 8 warps x 8 rows, float4 coalesced, STS.128 conflict-free
    const float* hsrc = hin + (size_t)blockIdx.x * 64 * 256;
#pragma unroll
    for (int rr = 0; rr < 8; rr++) {
        int r = warp*8 + rr;
        float4 v = ((const float4*)(hsrc + r*256))[lane];
        uint4 uv = make_uint4(tf32u(v.x), tf32u(v.y), tf32u(v.z), tf32u(v.w));
        *(uint4*)(As + r*260 + lane*4) = uv;
    }
    // load B (twiddle matrix, L2-hot)
#pragma unroll
    for (int rep = 0; rep < 32; rep++) {
        int j = rep*256 + t;
        int w = j >> 5, c = j & 31;
        Bs[w*40 + c] = tf32u(g_E256[j]);
    }
    __syncthreads();

    int warpM = warp >> 2, warpN = warp & 3;   // 2M x 4N warp grid
    int m0 = warpM*32, n0 = warpN*8;

    float acc[2][4] = {};
#pragma unroll
    for (int ks = 0; ks < 32; ks++) {
        int k0 = ks*8;
        uint a[2][4], bf[2];
#pragma unroll
        for (int mi = 0; mi < 2; mi++) {
            int r = m0 + mi*16 + gr;
            a[mi][0] = As[r*260     + k0+gc];
            a[mi][1] = As[(r+8)*260 + k0+gc];
            a[mi][2] = As[r*260     + k0+gc+4];
            a[mi][3] = As[(r+8)*260 + k0+gc+4];
        }
        bf[0] = Bs[(k0+gc)*40   + n0+gr];
        bf[1] = Bs[(k0+gc+4)*40 + n0+gr];
#pragma unroll
        for (int mi = 0; mi < 2; mi++) MMA_TF32(acc[mi], a[mi], bf);
    }

    // epilogue: cols (2ky, 2ky+1) = (Tr, Ti) -> g_T[bi][ky][h]
    int bi = blockIdx.x >> 2;
    int h0 = (blockIdx.x & 3) * 64;
    int ky = (n0 >> 1) + gc;
    float2* Tg = g_T + (size_t)bi*4096 + ky*256;
#pragma unroll
    for (int mi = 0; mi < 2; mi++)
#pragma unroll
        for (int ep = 0; ep < 2; ep++) {
            int h = h0 + m0 + mi*16 + gr + ep*8;
            Tg[h] = make_float2(acc[mi][2*ep], acc[mi][2*ep+1]);
        }
}

// ---------------- forward DFT over H as tf32 MMA ----------------
// A = [cos(32 rows); sin(32 rows)][256 h]  (constant), B = T components per bi.
// P = A x B; re = P[kx][2ky] + P[32+kx][2ky+1]; im = P[kx][2ky+1] - P[32+kx][2ky]
#define DFTH_SMEM ((64*260 + 2*256*40) * 4)
__global__ __launch_bounds__(256) void k_dfth() {
    extern __shared__ uint sm[];
    uint* As = sm;               // twiddles [m=64][k=256] stride 260
    uint* Bs = sm + 64*260;      // 2 x [k=256][n=32] stride 40
    int t = threadIdx.x, lane = t & 31, warp = t >> 5;
    int gr = lane >> 2, gc = lane & 3;

    for (int j = t; j < 16384; j += 256) {
        int m = j >> 8, h = j & 255;
        float v = (m < 32) ? g_ch[m*256 + h] : g_sh[(m-32)*256 + h];
        As[m*260 + h] = tf32u(v);
    }
#pragma unroll
    for (int half = 0; half < 2; half++) {
        const float2* Tg = g_T + (size_t)(blockIdx.x*2 + half)*4096;
        uint* Bh = Bs + half*(256*40);
        for (int j = t; j < 4096; j += 256) {
            int ky = j >> 8, h = j & 255;
            float2 v = Tg[j];
            Bh[h*40 + 2*ky]     = tf32u(v.x);
            Bh[h*40 + 2*ky + 1] = tf32u(v.y);
        }
    }
    __syncthreads();

    int halfsel = warp >> 2;                  // warps 0-3: bi0, 4-7: bi1
    int n0 = (warp & 3) * 8;
    const uint* Bh = Bs + halfsel*(256*40);

    float acc[4][4] = {};
#pragma unroll
    for (int ks = 0; ks < 32; ks++) {
        int k0 = ks*8;
        uint a[4][4], bf[2];
#pragma unroll
        for (int mi = 0; mi < 4; mi++) {
            int r = mi*16 + gr;
            a[mi][0] = As[r*260     + k0+gc];
            a[mi][1] = As[(r+8)*260 + k0+gc];
            a[mi][2] = As[r*260     + k0+gc+4];
            a[mi][3] = As[(r+8)*260 + k0+gc+4];
        }
        bf[0] = Bh[(k0+gc)*40   + n0+gr];
        bf[1] = Bh[(k0+gc+4)*40 + n0+gr];
#pragma unroll
        for (int mi = 0; mi < 4; mi++) MMA_TF32(acc[mi], a[mi], bf);
    }

    int bi = blockIdx.x*2 + halfsel;
    int b = bi >> 6, i = bi & 63;
    int ky = (n0 >> 1) + gc;
#pragma unroll
    for (int mi = 0; mi < 2; mi++)
#pragma unroll
        for (int ep = 0; ep < 2; ep++) {
            int kx = mi*16 + gr + ep*8;
            float re = acc[mi][2*ep]     + acc[mi+2][2*ep+1];
            float im = acc[mi][2*ep+1]   - acc[mi+2][2*ep];
            g_Xf[((size_t)(kx*16 + ky)*16 + b)*64 + i] = make_float2(re, im);
        }
}

// ---------------- per-mode complex GEMM ----------------
__global__ __launch_bounds__(256) void k_modemix(const float* __restrict__ w1r, const float* __restrict__ w1i,
                                                 const float* __restrict__ w2r, const float* __restrict__ w2i,
                                                 int layer) {
    __shared__ float2 Xs[16*64];
    __shared__ float2 Ws[64*64];
    int mode = blockIdx.x;
    int kx = mode >> 4, ky = mode & 15;
    int t = threadIdx.x;

    const float2* Xg = g_Xf + (size_t)mode * 1024;
    for (int j = t; j < 1024; j += 256) Xs[j] = Xg[j];

    const float* wr; const float* wi; int kxp;
    if (kx < 16) { wr = w1r; wi = w1i; kxp = kx; }
    else         { wr = w2r; wi = w2i; kxp = kx - 16; }
    size_t base = (size_t)layer * (NWID*NWID*256) + (size_t)kxp*16 + ky;
    for (int j = t; j < 4096; j += 256) {
        Ws[j] = make_float2(wr[base + (size_t)j*256], wi[base + (size_t)j*256]);
    }
    __syncthreads();

#pragma unroll
    for (int r = 0; r < 4; r++) {
        int oid = t + 256*r;
        int b = oid >> 6, o = oid & 63;
        float re = 0.f, im = 0.f;
#pragma unroll 8
        for (int i = 0; i < 64; i++) {
            float2 X = Xs[b*64 + i];
            float2 W = Ws[i*64 + o];
            re = fmaf(X.x, W.x, fmaf(-X.y, W.y, re));
            im = fmaf(X.x, W.y, fmaf( X.y, W.x, im));
        }
        g_Xo[((size_t)(b*64 + o)*16 + ky)*32 + kx] = make_float2(re, im);
    }
}

// ---------------- inverse DFT over H ----------------
__global__ __launch_bounds__(256) void k_idfth() {
    __shared__ float2 Xs[16*32];
    int bo = blockIdx.x;
    int t = threadIdx.x;
    {
        const float4* Xg4 = (const float4*)(g_Xo + (size_t)bo * 512);
        float4* Xs4 = (float4*)Xs;
        for (int j = t; j < 256; j += 256) Xs4[j] = Xg4[j];
    }
    __syncthreads();

    float cth[32], sth[32];
#pragma unroll
    for (int k = 0; k < 32; k++) { cth[k] = g_ch[k*256 + t]; sth[k] = g_sh[k*256 + t]; }

    const float scale = 1.0f / 65536.0f;
#pragma unroll 2
    for (int ky = 0; ky < 16; ky++) {
        float re = 0.f, im = 0.f;
#pragma unroll
        for (int k = 0; k < 32; k++) {
            float2 X = Xs[ky*32 + k];
            re = fmaf(X.x, cth[k], fmaf(-X.y, sth[k], re));
            im = fmaf(X.x, sth[k], fmaf( X.y, cth[k], im));
        }
        g_Z[((size_t)bo*256 + t)*16 + ky] = make_float2(re*scale, im*scale);
    }
}

// ---------------- k_final as tf32 MMA GEMM ----------------
#define KF_SMEM_BYTES ((96*136 + 96*72 + 64) * 4)
__global__ __launch_bounds__(256) void k_final(int srcsel,
                                               const float* __restrict__ pw_w,
                                               const float* __restrict__ pw_b,
                                               int layer, int apply_gelu) {
    const float* __restrict__ hin  = srcsel ? g_h1 : g_h0;
    float*       __restrict__ hout = srcsel ? g_h0 : g_h1;

    extern __shared__ uint smem_u[];
    uint*  As  = smem_u;                       // [k][w] stride 136
    uint*  Bs  = smem_u + 96*136;              // [k][o] stride 72
    float* pbs = (float*)(smem_u + 96*136 + 96*72);

    int t = threadIdx.x;
    int lane = t & 31, warp = t >> 5;
    int bx = blockIdx.x;                       // 8192 = b(16) * p(256) * half(2)
    int b = bx >> 9, p = (bx >> 1) & 255, half = bx & 1;
    int w0 = half * 128;

    const float* hsrc = hin + (size_t)(b*64)*NPIX + (size_t)p*256 + w0;
#pragma unroll
    for (int rr = 0; rr < 8; rr++) {
        int i = warp*8 + rr;
        float4 v = *(const float4*)(hsrc + (size_t)i*NPIX + lane*4);
        uint4 uv = make_uint4(tf32u(v.x), tf32u(v.y), tf32u(v.z), tf32u(v.w));
        *(uint4*)(As + i*136 + lane*4) = uv;
    }
#pragma unroll
    for (int rep = 0; rep < 16; rep++) {
        int j = rep*256 + t;                   // 4096 = e(32) * w(128)
        int e = j >> 7, w = j & 127;
        int q = e >> 1;
        float v = (e & 1) ? -g_sw[q*256 + w0 + w] : g_cw[q*256 + w0 + w];
        As[(64 + e)*136 + w] = tf32u(v);
    }
    const float* pwg = pw_w + (size_t)layer * 4096;
#pragma unroll
    for (int rep = 0; rep < 16; rep++) {
        int j = rep*256 + t;                   // 4096 = o*64 + i
        int o = j >> 6, i = j & 63;
        Bs[i*72 + o] = tf32u(pwg[j]);
    }
#pragma unroll
    for (int rep = 0; rep < 4; rep++) {
        int j = rep*256 + t;                   // 1024 = o*16 + q
        int o = j >> 4, q = j & 15;
        float2 z = g_Z[((size_t)(b*64 + o)*256 + p)*16 + q];
        float a = q ? 2.f : 1.f;
        Bs[(64 + 2*q    )*72 + o] = tf32u(a * z.x);
        Bs[(64 + 2*q + 1)*72 + o] = tf32u(a * z.y);
    }
    if (t < 64) pbs[t] = pw_b[layer*64 + t];
    __syncthreads();

    int warpM = warp & 3, warpN = warp >> 2;
    int m0 = warpM * 32, n0 = warpN * 32;
    int gr = lane >> 2, gc = lane & 3;

    float acc[2][4][4];
#pragma unroll
    for (int mi = 0; mi < 2; mi++)
#pragma unroll
        for (int ni = 0; ni < 4; ni++)
#pragma unroll
            for (int e = 0; e < 4; e++) acc[mi][ni][e] = 0.f;

#pragma unroll
    for (int ks = 0; ks < 12; ks++) {
        int k0 = ks * 8;
        uint a[2][4];
#pragma unroll
        for (int mi = 0; mi < 2; mi++) {
            int r = m0 + mi*16 + gr;
            a[mi][0] = As[(k0 + gc    )*136 + r];
            a[mi][1] = As[(k0 + gc    )*136 + r + 8];
            a[mi][2] = As[(k0 + gc + 4)*136 + r];
            a[mi][3] = As[(k0 + gc + 4)*136 + r + 8];
        }
        uint bf[4][2];
#pragma unroll
        for (int ni = 0; ni < 4; ni++) {
            int n = n0 + ni*8 + gr;
            bf[ni][0] = Bs[(k0 + gc    )*72 + n];
            bf[ni][1] = Bs[(k0 + gc + 4)*72 + n];
        }
#pragma unroll
        for (int mi = 0; mi < 2; mi++)
#pragma unroll
            for (int ni = 0; ni < 4; ni++)
                MMA_TF32(acc[mi][ni], a[mi], bf[ni]);
    }

    size_t outbase = (size_t)(b*64)*NPIX + (size_t)p*256 + w0;
#pragma unroll
    for (int mi = 0; mi < 2; mi++)
#pragma unroll
        for (int ni = 0; ni < 4; ni++)
#pragma unroll
            for (int e = 0; e < 4; e++) {
                int row = m0 + mi*16 + gr + (e >> 1)*8;
                int col = n0 + ni*8 + 2*gc + (e & 1);
                float val = acc[mi][ni][e] + pbs[col];
                if (apply_gelu) val = gelu_f(val);
                hout[outbase + (size_t)col*NPIX + row] = val;
            }
}

// ---------------- fc1+GELU+fc2 as tf32 MMA ----------------
#define KFC_SMEM_BYTES ((128*136 + 128*40 + 128 + 32) * 4)
__global__ __launch_bounds__(256) void k_fc12(float* __restrict__ out,
                                              const float* __restrict__ fc1w, const float* __restrict__ fc1b,
                                              const float* __restrict__ fc2w, const float* __restrict__ fc2b) {
    extern __shared__ uint smem_u[];
    uint*  As  = smem_u;                        // [i][w] stride 136 (k-major)
    uint*  Bs1 = smem_u + 64*136;               // [i][j] stride 136
    uint*  Hs  = smem_u;                        // [j][w] stride 136 (overlaps)
    uint*  Bs2 = smem_u + 128*136;              // [j][o] stride 40
    float* b1s = (float*)(smem_u + 128*136 + 128*40);
    float* b2s = b1s + 128;

    int t = threadIdx.x;
    int lane = t & 31, warp = t >> 5;
    int bx = blockIdx.x;
    int b = bx >> 9, p = (bx >> 1) & 255, half = bx & 1;
    int w0 = half * 128;

    const float* hsrc = g_h0 + (size_t)(b*64)*NPIX + (size_t)p*256 + w0;
#pragma unroll
    for (int rr = 0; rr < 8; rr++) {
        int i = warp*8 + rr;
        float4 v = *(const float4*)(hsrc + (size_t)i*NPIX + lane*4);
        uint4 uv = make_uint4(tf32u(v.x), tf32u(v.y), tf32u(v.z), tf32u(v.w));
        *(uint4*)(As + i*136 + lane*4) = uv;
    }
#pragma unroll
    for (int rep = 0; rep < 32; rep++) {
        int j2 = rep*256 + t;                  // 8192 = j*64 + i
        int jj = j2 >> 6, i = j2 & 63;
        Bs1[i*136 + jj] = tf32u(fc1w[j2]);
    }
#pragma unroll
    for (int rep = 0; rep < 12; rep++) {
        int j2 = rep*256 + t;
        int jj = j2 / 24, o = j2 - jj*24;
        float v = (o < 20) ? fc2w[o*FCH + jj] : 0.f;
        Bs2[jj*40 + o] = tf32u(v);
    }
    if (t < FCH)   b1s[t] = fc1b[t];
    if (t < NCOUT) b2s[t] = fc2b[t];
    __syncthreads();

    int gr = lane >> 2, gc = lane & 3;

    int warpM = warp & 1, warpN = warp >> 1;
    int m0 = warpM * 64, n0 = warpN * 32;
    float acc1[4][4][4];
#pragma unroll
    for (int mi = 0; mi < 4; mi++)
#pragma unroll
        for (int ni = 0; ni < 4; ni++)
#pragma unroll
            for (int e = 0; e < 4; e++) acc1[mi][ni][e] = 0.f;

#pragma unroll
    for (int ks = 0; ks < 8; ks++) {
        int k0 = ks * 8;
        uint a[4][4];
#pragma unroll
        for (int mi = 0; mi < 4; mi++) {
            int r = m0 + mi*16 + gr;
            a[mi][0] = As[(k0 + gc    )*136 + r];
            a[mi][1] = As[(k0 + gc    )*136 + r + 8];
            a[mi][2] = As[(k0 + gc + 4)*136 + r];
            a[mi][3] = As[(k0 + gc + 4)*136 + r + 8];
        }
        uint bf[4][2];
#pragma unroll
        for (int ni = 0; ni < 4; ni++) {
            int n = n0 + ni*8 + gr;
            bf[ni][0] = Bs1[(k0 + gc    )*136 + n];
            bf[ni][1] = Bs1[(k0 + gc + 4)*136 + n];
        }
#pragma unroll
        for (int mi = 0; mi < 4; mi++)
#pragma unroll
            for (int ni = 0; ni < 4; ni++)
                MMA_TF32(acc1[mi][ni], a[mi], bf[ni]);
    }

    __syncthreads();

#pragma unroll
    for (int mi = 0; mi < 4; mi++)
#pragma unroll
        for (int ni = 0; ni < 4; ni++)
#pragma unroll
            for (int e = 0; e < 4; e++) {
                int row = m0 + mi*16 + gr + (e >> 1)*8;
                int col = n0 + ni*8 + 2*gc + (e & 1);
                float v = gelu_f(acc1[mi][ni][e] + b1s[col]);
                Hs[col*136 + row] = tf32u(v);
            }
    __syncthreads();

    int m0b = warp * 16;
    float acc2[3][4];
#pragma unroll
    for (int ni = 0; ni < 3; ni++)
#pragma unroll
        for (int e = 0; e < 4; e++) acc2[ni][e] = 0.f;

#pragma unroll
    for (int ks = 0; ks < 16; ks++) {
        int k0 = ks * 8;
        uint a[4];
        {
            int r = m0b + gr;
            a[0] = Hs[(k0 + gc    )*136 + r];
            a[1] = Hs[(k0 + gc    )*136 + r + 8];
            a[2] = Hs[(k0 + gc + 4)*136 + r];
            a[3] = Hs[(k0 + gc + 4)*136 + r + 8];
        }
        uint bf[3][2];
#pragma unroll
        for (int ni = 0; ni < 3; ni++) {
            int n = ni*8 + gr;
            bf[ni][0] = Bs2[(k0 + gc    )*40 + n];
            bf[ni][1] = Bs2[(k0 + gc + 4)*40 + n];
        }
#pragma unroll
        for (int ni = 0; ni < 3; ni++)
            MMA_TF32(acc2[ni], a, bf[ni]);
    }

    size_t outbase = (size_t)(b*NCOUT)*NPIX + (size_t)p*256 + w0;
#pragma unroll
    for (int ni = 0; ni < 3; ni++)
#pragma unroll
        for (int e = 0; e < 4; e++) {
            int row = m0b + gr + (e >> 1)*8;
            int col = ni*8 + 2*gc + (e & 1);
            if (col < NCOUT)
                out[outbase + (size_t)col*NPIX + row] = acc2[ni][e] + b2s[col];
        }
}

// ---------------- launch ----------------
extern "C" void kernel_launch(void* const* d_in, const int* in_sizes, int n_in,
                              void* d_out, int out_size) {
    const float* x    = (const float*)d_in[0];
    const float* w1r  = (const float*)d_in[1];
    const float* w1i  = (const float*)d_in[2];
    const float* w2r  = (const float*)d_in[3];
    const float* w2i  = (const float*)d_in[4];
    const float* pw_w = (const float*)d_in[5];
    const float* pw_b = (const float*)d_in[6];
    const float* fc0w = (const float*)d_in[7];
    const float* fc0b = (const float*)d_in[8];
    const float* fc1w = (const float*)d_in[9];
    const float* fc1b = (const float*)d_in[10];
    const float* fc2w = (const float*)d_in[11];
    const float* fc2b = (const float*)d_in[12];
    float* out = (float*)d_out;

    cudaFuncSetAttribute(k_final, cudaFuncAttributeMaxDynamicSharedMemorySize, KF_SMEM_BYTES);
    cudaFuncSetAttribute(k_fc12,  cudaFuncAttributeMaxDynamicSharedMemorySize, KFC_SMEM_BYTES);
    cudaFuncSetAttribute(k_dftw,  cudaFuncAttributeMaxDynamicSharedMemorySize, DFTW_SMEM);
    cudaFuncSetAttribute(k_dfth,  cudaFuncAttributeMaxDynamicSharedMemorySize, DFTH_SMEM);

    k_init_tables<<<32, 256>>>();
    k_fc0<<<4096, 256>>>(x, fc0w, fc0b);

    for (int l = 0; l < NLAY; l++) {
        int src = l & 1;
        k_dftw<<<4096, 256, DFTW_SMEM>>>(src);
        k_dfth<<<512, 256, DFTH_SMEM>>>();
        k_modemix<<<512, 256>>>(w1r, w1i, w2r, w2i, l);
        k_idfth<<<1024, 256>>>();
        k_final<<<8192, 256, KF_SMEM_BYTES>>>(src, pw_w, pw_b, l, (l < 3) ? 1 : 0);
    }
    // after l=3 (src=1), result lives in g_h0
    k_fc12<<<8192, 256, KFC_SMEM_BYTES>>>(out, fc1w, fc1b, fc2w, fc2b);
}

// round 12
// speedup vs baseline: 1.6215x; 1.0061x over previous
#include <cuda_runtime.h>
#include <math.h>

// ---------------- problem constants ----------------
#define NB    16
#define NCIN  20
#define NWID  64
#define NPIX  65536      // 256*256
#define NLAY  4
#define M1    16
#define M2    16
#define FCH   128
#define NCOUT 20

typedef unsigned long long ull;
typedef unsigned int uint;

// ---- packed f32x2 helpers ----
__device__ __forceinline__ ull ffma2(ull a, ull b, ull c) {
    ull d; asm("fma.rn.f32x2 %0, %1, %2, %3;" : "=l"(d) : "l"(a), "l"(b), "l"(c)); return d;
}
__device__ __forceinline__ ull add2(ull a, ull b) {
    ull d; asm("add.rn.f32x2 %0, %1, %2;" : "=l"(d) : "l"(a), "l"(b)); return d;
}
__device__ __forceinline__ ull pk2(float lo, float hi) {
    ull r; asm("mov.b64 %0, {%1,%2};" : "=l"(r) : "f"(lo), "f"(hi)); return r;
}
__device__ __forceinline__ float2 up2(ull v) {
    float2 r; asm("mov.b64 {%0,%1}, %2;" : "=f"(r.x), "=f"(r.y) : "l"(v)); return r;
}

// ---- tf32 mma helpers ----
__device__ __forceinline__ uint tf32u(float x) {
    uint y; asm("cvt.rna.tf32.f32 %0, %1;" : "=r"(y) : "f"(x)); return y;
}
#define MMA_TF32(d, a, b) \
    asm volatile("mma.sync.aligned.m16n8k8.row.col.f32.tf32.tf32.f32 " \
                 "{%0,%1,%2,%3}, {%4,%5,%6,%7}, {%8,%9}, {%0,%1,%2,%3};" \
                 : "+f"((d)[0]), "+f"((d)[1]), "+f"((d)[2]), "+f"((d)[3]) \
                 : "r"((a)[0]), "r"((a)[1]), "r"((a)[2]), "r"((a)[3]), \
                   "r"((b)[0]), "r"((b)[1]))

__device__ __forceinline__ float gelu_f(float v) {
    return 0.5f * v * (1.f + erff(v * 0.70710678118654752f));
}

// ---------------- device scratch (no allocations allowed) ----------------
__device__ float  g_h0[NB*NWID*NPIX];          // 256 MB ping
__device__ float  g_h1[NB*NWID*NPIX];          // 256 MB pong
__device__ float2 g_T  [NB*NWID*16*256];       // fwd stage1: [b][i][ky][h]
__device__ float2 g_Xf [32*16*NB*NWID];        // fwd modes:  [kx][ky][b][i]
__device__ float2 g_Xo [NB*NWID*16*32];        // mixed:      [b][o][ky][kx]
__device__ float2 g_Z  [NB*NWID*256*16];       // inv stage1: [b][o][p][ky]
// twiddle tables
__device__ float g_cw[16*256], g_sw[16*256];   // cos/sin(2*pi*ky*w/256)  [ky][w]
__device__ float g_ch[32*256], g_sh[32*256];   // cos/sin(2*pi*kx*h/256)  [k][h]
// folded DFT-W twiddles: rows 0-127: even ky (0,2,..,14), rows 128-255: odd ky.
// col c: ky_class = 2*(c>>1) + (row>=128); value = (c&1) ? -sin(2pi*ky*w/256) : cos
__device__ float g_E2[256*16];

// ---------------- table init ----------------
__global__ __launch_bounds__(256) void k_init_tables() {
    int id = blockIdx.x * 256 + threadIdx.x;   // 8192 threads
    if (id < 16*256) {
        int ky = id >> 8, w = id & 255;
        float s, c;
        sincospif((float)(ky * w) * (1.0f/128.0f), &s, &c);
        g_cw[id] = c; g_sw[id] = s;
    }
    if (id < 32*256) {
        int k = id >> 8, h = id & 255;
        int kx = (k < 16) ? k : (224 + k);
        float s, c;
        sincospif((float)(kx * h) * (1.0f/128.0f), &s, &c);
        g_ch[id] = c; g_sh[id] = s;
    }
    if (id < 256*16) {
        int r = id >> 4, c = id & 15;
        int w = r & 127;
        int ky = 2*(c >> 1) + (r >> 7);
        float s, cv;
        sincospif((float)(ky * w) * (1.0f/128.0f), &s, &cv);
        g_E2[id] = (c & 1) ? -s : cv;
    }
}

// ---------------- lift: h0[b,d,pix] ----------------
__global__ __launch_bounds__(256) void k_fc0(const float* __restrict__ x,
                                             const float* __restrict__ w,
                                             const float* __restrict__ bias) {
    __shared__ float ws[NWID*NCIN];
    __shared__ float bs[NWID];
    int t = threadIdx.x;
    for (int j = t; j < NWID*NCIN; j += 256) ws[j] = w[j];
    if (t < NWID) bs[t] = bias[t];
    __syncthreads();

    int idx = blockIdx.x * 256 + t;
    int b = idx >> 16, pix = idx & 65535;
    ull xin2[10];
#pragma unroll
    for (int q = 0; q < 10; q++) {
        float x0 = x[(size_t)(b*NCIN + 2*q    )*NPIX + pix];
        float x1 = x[(size_t)(b*NCIN + 2*q + 1)*NPIX + pix];
        xin2[q] = pk2(x0, x1);
    }
#pragma unroll 4
    for (int d = 0; d < NWID; d++) {
        const ulonglong2* wp = (const ulonglong2*)(ws + d*NCIN);
        ull a0 = 0ULL, a1 = 0ULL;
#pragma unroll
        for (int q = 0; q < 5; q++) {
            ulonglong2 ww = wp[q];
            a0 = ffma2(xin2[2*q],   ww.x, a0);
            a1 = ffma2(xin2[2*q+1], ww.y, a1);
        }
        float2 u = up2(add2(a0, a1));
        g_h0[(size_t)(b*NWID + d)*NPIX + pix] = u.x + u.y + bs[d];
    }
}

// ---------------- forward DFT over W: radix-2 fold + 3xTF32 split MMA ----------------
// Per block: 64 rows (h of one bi). Even-ky GEMM: F0[64x128] x Ee[128x16];
// odd-ky: F1 x Eo. 3xTF32 split gives near-fp32 accuracy.
#define DFTW_SMEM ((64*260 + 256*24) * 4)
__global__ __launch_bounds__(256) void k_dftw(int srcsel) {
    const float* __restrict__ hin = srcsel ? g_h1 : g_h0;
    extern __shared__ float smf[];
    float* As = smf;              // [row 64][col 256] fp32: cols 0-127 = F0, 128-255 = F1
    float* Bs = smf + 64*260;     // [k 256][n 16] stride 24 fp32
    int t = threadIdx.x, lane = t & 31, warp = t >> 5;
    int gr = lane >> 2, gc = lane & 3;

    const float* hsrc = hin + (size_t)blockIdx.x * 64 * 256;
#pragma unroll
    for (int rr = 0; rr < 8; rr++) {
        int r = warp*8 + rr;
        float4 lo = ((const float4*)(hsrc + r*256))[lane];
        float4 hi = ((const float4*)(hsrc + r*256))[lane + 32];
        float4 F0 = make_float4(lo.x+hi.x, lo.y+hi.y, lo.z+hi.z, lo.w+hi.w);
        float4 F1 = make_float4(lo.x-hi.x, lo.y-hi.y, lo.z-hi.z, lo.w-hi.w);
        *(float4*)(As + r*260 +       lane*4) = F0;
        *(float4*)(As + r*260 + 128 + lane*4) = F1;
    }
#pragma unroll
    for (int rep = 0; rep < 16; rep++) {
        int j = rep*256 + t;      // 4096 entries
        Bs[(j >> 4)*24 + (j & 15)] = g_E2[j];
    }
    __syncthreads();

    int grp = warp >> 2;          // 0: even ky (uses F0 / rows 0-127), 1: odd ky
    int wl  = warp & 3;
    int m0 = (wl & 1) * 32;
    int n0 = (wl >> 1) * 8;
    int kb = grp * 128;

    float accA[2][4] = {}, accB[2][4] = {};
#pragma unroll
    for (int ks = 0; ks < 16; ks++) {
        int k0 = kb + ks*8;
        uint ah[2][4], al[2][4];
#pragma unroll
        for (int mi = 0; mi < 2; mi++) {
            int r = m0 + mi*16 + gr;
#pragma unroll
            for (int j = 0; j < 4; j++) {
                int rr = r + (j & 1)*8;
                int kk = k0 + gc + (j >> 1)*4;
                float v = As[rr*260 + kk];
                uint h = tf32u(v);
                ah[mi][j] = h;
                al[mi][j] = tf32u(v - __uint_as_float(h));
            }
        }
        uint bh[2], bl[2];
#pragma unroll
        for (int j = 0; j < 2; j++) {
            float v = Bs[(k0 + gc + j*4)*24 + n0 + gr];
            uint h = tf32u(v);
            bh[j] = h;
            bl[j] = tf32u(v - __uint_as_float(h));
        }
#pragma unroll
        for (int mi = 0; mi < 2; mi++) {
            MMA_TF32(accA[mi], ah[mi], bh);
            MMA_TF32(accB[mi], ah[mi], bl);
            MMA_TF32(accB[mi], al[mi], bh);
        }
    }

    int bi = blockIdx.x >> 2;
    int h0 = (blockIdx.x & 3) * 64;
    int kyi = (n0 >> 1) + gc;          // 0..7
    int ky  = 2*kyi + grp;
    float2* Tg = g_T + (size_t)bi*4096 + ky*256;
#pragma unroll
    for (int mi = 0; mi < 2; mi++)
#pragma unroll
        for (int ep = 0; ep < 2; ep++) {
            int h = h0 + m0 + mi*16 + gr + ep*8;
            float re = accA[mi][2*ep]   + accB[mi][2*ep];
            float im = accA[mi][2*ep+1] + accB[mi][2*ep+1];
            Tg[h] = make_float2(re, im);
        }
}

// ---------------- forward DFT over H: fp32 rotation + radix-2 fold ----------------
// X[kx] = sum_{h<128} (T[h] + (-1)^kx T[h+128]) e^{-2pi i kx h/256}
__global__ __launch_bounds__(256) void k_dfth() {
    __shared__ float2 Ts[2*2048 + 4];   // even plane at 0, odd plane at 2052 (bank-shifted)
    int bi = blockIdx.x;                // b*64 + i (1024 blocks)
    int t = threadIdx.x;
    const float2* Tg = g_T + (size_t)bi * 4096;
    for (int j = t; j < 2048; j += 256) {
        int ky = j >> 7, h = j & 127;
        float2 u = Tg[ky*256 + h];
        float2 v = Tg[ky*256 + h + 128];
        Ts[j]        = make_float2(u.x + v.x, u.y + v.y);
        Ts[2052 + j] = make_float2(u.x - v.x, u.y - v.y);
    }
    __syncthreads();

    int k  = t & 31;                    // k index: 0-15 -> kx=k, 16-31 -> kx=224+k
    int ky = t >> 5;                    // 0..7; thread also does ky+8
    int b = bi >> 6, i = bi & 63;
    int pb = (k & 1) ? 2052 : 0;        // parity of kx == parity of k

    float c0 = g_ch[k*256 + 1], s0 = g_sh[k*256 + 1];
    float c = 1.f, s = 0.f;
    float re0 = 0.f, im0 = 0.f, re1 = 0.f, im1 = 0.f;
#pragma unroll 4
    for (int h = 0; h < 128; h++) {
        float2 a  = Ts[pb + ky*128 + h];
        float2 bq = Ts[pb + (ky + 8)*128 + h];
        re0 = fmaf(a.x,  c, fmaf( a.y,  s, re0));
        im0 = fmaf(a.y,  c, fmaf(-a.x,  s, im0));
        re1 = fmaf(bq.x, c, fmaf( bq.y, s, re1));
        im1 = fmaf(bq.y, c, fmaf(-bq.x, s, im1));
        float cn = fmaf(-s, s0, c*c0);
        float sn = fmaf( c, s0, s*c0);
        c = cn; s = sn;
    }
    g_Xf[((size_t)(k*16 + ky    )*16 + b)*64 + i] = make_float2(re0, im0);
    g_Xf[((size_t)(k*16 + ky + 8)*16 + b)*64 + i] = make_float2(re1, im1);
}

// ---------------- per-mode complex GEMM ----------------
__global__ __launch_bounds__(256) void k_modemix(const float* __restrict__ w1r, const float* __restrict__ w1i,
                                                 const float* __restrict__ w2r, const float* __restrict__ w2i,
                                                 int layer) {
    __shared__ float2 Xs[16*64];
    __shared__ float2 Ws[64*64];
    int mode = blockIdx.x;
    int kx = mode >> 4, ky = mode & 15;
    int t = threadIdx.x;

    const float2* Xg = g_Xf + (size_t)mode * 1024;
    for (int j = t; j < 1024; j += 256) Xs[j] = Xg[j];

    const float* wr; const float* wi; int kxp;
    if (kx < 16) { wr = w1r; wi = w1i; kxp = kx; }
    else         { wr = w2r; wi = w2i; kxp = kx - 16; }
    size_t base = (size_t)layer * (NWID*NWID*256) + (size_t)kxp*16 + ky;
    for (int j = t; j < 4096; j += 256) {
        Ws[j] = make_float2(wr[base + (size_t)j*256], wi[base + (size_t)j*256]);
    }
    __syncthreads();

#pragma unroll
    for (int r = 0; r < 4; r++) {
        int oid = t + 256*r;
        int b = oid >> 6, o = oid & 63;
        float re = 0.f, im = 0.f;
#pragma unroll 8
        for (int i = 0; i < 64; i++) {
            float2 X = Xs[b*64 + i];
            float2 W = Ws[i*64 + o];
            re = fmaf(X.x, W.x, fmaf(-X.y, W.y, re));
            im = fmaf(X.x, W.y, fmaf( X.y, W.x, im));
        }
        g_Xo[((size_t)(b*64 + o)*16 + ky)*32 + kx] = make_float2(re, im);
    }
}

// ---------------- inverse DFT over H ----------------
__global__ __launch_bounds__(256) void k_idfth() {
    __shared__ float2 Xs[16*32];
    int bo = blockIdx.x;
    int t = threadIdx.x;
    {
        const float4* Xg4 = (const float4*)(g_Xo + (size_t)bo * 512);
        float4* Xs4 = (float4*)Xs;
        for (int j = t; j < 256; j += 256) Xs4[j] = Xg4[j];
    }
    __syncthreads();

    float cth[32], sth[32];
#pragma unroll
    for (int k = 0; k < 32; k++) { cth[k] = g_ch[k*256 + t]; sth[k] = g_sh[k*256 + t]; }

    const float scale = 1.0f / 65536.0f;
#pragma unroll 2
    for (int ky = 0; ky < 16; ky++) {
        float re = 0.f, im = 0.f;
#pragma unroll
        for (int k = 0; k < 32; k++) {
            float2 X = Xs[ky*32 + k];
            re = fmaf(X.x, cth[k], fmaf(-X.y, sth[k], re));
            im = fmaf(X.x, sth[k], fmaf( X.y, cth[k], im));
        }
        g_Z[((size_t)bo*256 + t)*16 + ky] = make_float2(re*scale, im*scale);
    }
}

// ---------------- k_final as tf32 MMA GEMM ----------------
#define KF_SMEM_BYTES ((96*136 + 96*72 + 64) * 4)
__global__ __launch_bounds__(256) void k_final(int srcsel,
                                               const float* __restrict__ pw_w,
                                               const float* __restrict__ pw_b,
                                               int layer, int apply_gelu) {
    const float* __restrict__ hin  = srcsel ? g_h1 : g_h0;
    float*       __restrict__ hout = srcsel ? g_h0 : g_h1;

    extern __shared__ uint smem_u[];
    uint*  As  = smem_u;                       // [k][w] stride 136
    uint*  Bs  = smem_u + 96*136;              // [k][o] stride 72
    float* pbs = (float*)(smem_u + 96*136 + 96*72);

    int t = threadIdx.x;
    int lane = t & 31, warp = t >> 5;
    int bx = blockIdx.x;                       // 8192 = b(16) * p(256) * half(2)
    int b = bx >> 9, p = (bx >> 1) & 255, half = bx & 1;
    int w0 = half * 128;

    const float* hsrc = hin + (size_t)(b*64)*NPIX + (size_t)p*256 + w0;
#pragma unroll
    for (int rr = 0; rr < 8; rr++) {
        int i = warp*8 + rr;
        float4 v = *(const float4*)(hsrc + (size_t)i*NPIX + lane*4);
        uint4 uv = make_uint4(tf32u(v.x), tf32u(v.y), tf32u(v.z), tf32u(v.w));
        *(uint4*)(As + i*136 + lane*4) = uv;
    }
#pragma unroll
    for (int rep = 0; rep < 16; rep++) {
        int j = rep*256 + t;                   // 4096 = e(32) * w(128)
        int e = j >> 7, w = j & 127;
        int q = e >> 1;
        float v = (e & 1) ? -g_sw[q*256 + w0 + w] : g_cw[q*256 + w0 + w];
        As[(64 + e)*136 + w] = tf32u(v);
    }
    const float* pwg = pw_w + (size_t)layer * 4096;
#pragma unroll
    for (int rep = 0; rep < 16; rep++) {
        int j = rep*256 + t;                   // 4096 = o*64 + i
        int o = j >> 6, i = j & 63;
        Bs[i*72 + o] = tf32u(pwg[j]);
    }
#pragma unroll
    for (int rep = 0; rep < 4; rep++) {
        int j = rep*256 + t;                   // 1024 = o*16 + q
        int o = j >> 4, q = j & 15;
        float2 z = g_Z[((size_t)(b*64 + o)*256 + p)*16 + q];
        float a = q ? 2.f : 1.f;
        Bs[(64 + 2*q    )*72 + o] = tf32u(a * z.x);
        Bs[(64 + 2*q + 1)*72 + o] = tf32u(a * z.y);
    }
    if (t < 64) pbs[t] = pw_b[layer*64 + t];
    __syncthreads();

    int warpM = warp & 3, warpN = warp >> 2;
    int m0 = warpM * 32, n0 = warpN * 32;
    int gr = lane >> 2, gc = lane & 3;

    float acc[2][4][4];
#pragma unroll
    for (int mi = 0; mi < 2; mi++)
#pragma unroll
        for (int ni = 0; ni < 4; ni++)
#pragma unroll
            for (int e = 0; e < 4; e++) acc[mi][ni][e] = 0.f;

#pragma unroll
    for (int ks = 0; ks < 12; ks++) {
        int k0 = ks * 8;
        uint a[2][4];
#pragma unroll
        for (int mi = 0; mi < 2; mi++) {
            int r = m0 + mi*16 + gr;
            a[mi][0] = As[(k0 + gc    )*136 + r];
            a[mi][1] = As[(k0 + gc    )*136 + r + 8];
            a[mi][2] = As[(k0 + gc + 4)*136 + r];
            a[mi][3] = As[(k0 + gc + 4)*136 + r + 8];
        }
        uint bf[4][2];
#pragma unroll
        for (int ni = 0; ni < 4; ni++) {
            int n = n0 + ni*8 + gr;
            bf[ni][0] = Bs[(k0 + gc    )*72 + n];
            bf[ni][1] = Bs[(k0 + gc + 4)*72 + n];
        }
#pragma unroll
        for (int mi = 0; mi < 2; mi++)
#pragma unroll
            for (int ni = 0; ni < 4; ni++)
                MMA_TF32(acc[mi][ni], a[mi], bf[ni]);
    }

    size_t outbase = (size_t)(b*64)*NPIX + (size_t)p*256 + w0;
#pragma unroll
    for (int mi = 0; mi < 2; mi++)
#pragma unroll
        for (int ni = 0; ni < 4; ni++)
#pragma unroll
            for (int e = 0; e < 4; e++) {
                int row = m0 + mi*16 + gr + (e >> 1)*8;
                int col = n0 + ni*8 + 2*gc + (e & 1);
                float val = acc[mi][ni][e] + pbs[col];
                if (apply_gelu) val = gelu_f(val);
                hout[outbase + (size_t)col*NPIX + row] = val;
            }
}

// ---------------- fc1+GELU+fc2 as tf32 MMA ----------------
#define KFC_SMEM_BYTES ((128*136 + 128*40 + 128 + 32) * 4)
__global__ __launch_bounds__(256) void k_fc12(float* __restrict__ out,
                                              const float* __restrict__ fc1w, const float* __restrict__ fc1b,
                                              const float* __restrict__ fc2w, const float* __restrict__ fc2b) {
    extern __shared__ uint smem_u[];
    uint*  As  = smem_u;                        // [i][w] stride 136 (k-major)
    uint*  Bs1 = smem_u + 64*136;               // [i][j] stride 136
    uint*  Hs  = smem_u;                        // [j][w] stride 136 (overlaps)
    uint*  Bs2 = smem_u + 128*136;              // [j][o] stride 40
    float* b1s = (float*)(smem_u + 128*136 + 128*40);
    float* b2s = b1s + 128;

    int t = threadIdx.x;
    int lane = t & 31, warp = t >> 5;
    int bx = blockIdx.x;
    int b = bx >> 9, p = (bx >> 1) & 255, half = bx & 1;
    int w0 = half * 128;

    const float* hsrc = g_h0 + (size_t)(b*64)*NPIX + (size_t)p*256 + w0;
#pragma unroll
    for (int rr = 0; rr < 8; rr++) {
        int i = warp*8 + rr;
        float4 v = *(const float4*)(hsrc + (size_t)i*NPIX + lane*4);
        uint4 uv = make_uint4(tf32u(v.x), tf32u(v.y), tf32u(v.z), tf32u(v.w));
        *(uint4*)(As + i*136 + lane*4) = uv;
    }
#pragma unroll
    for (int rep = 0; rep < 32; rep++) {
        int j2 = rep*256 + t;                  // 8192 = j*64 + i
        int jj = j2 >> 6, i = j2 & 63;
        Bs1[i*136 + jj] = tf32u(fc1w[j2]);
    }
#pragma unroll
    for (int rep = 0; rep < 12; rep++) {
        int j2 = rep*256 + t;
        int jj = j2 / 24, o = j2 - jj*24;
        float v = (o < 20) ? fc2w[o*FCH + jj] : 0.f;
        Bs2[jj*40 + o] = tf32u(v);
    }
    if (t < FCH)   b1s[t] = fc1b[t];
    if (t < NCOUT) b2s[t] = fc2b[t];
    __syncthreads();

    int gr = lane >> 2, gc = lane & 3;

    int warpM = warp & 1, warpN = warp >> 1;
    int m0 = warpM * 64, n0 = warpN * 32;
    float acc1[4][4][4];
#pragma unroll
    for (int mi = 0; mi < 4; mi++)
#pragma unroll
        for (int ni = 0; ni < 4; ni++)
#pragma unroll
            for (int e = 0; e < 4; e++) acc1[mi][ni][e] = 0.f;

#pragma unroll
    for (int ks = 0; ks < 8; ks++) {
        int k0 = ks * 8;
        uint a[4][4];
#pragma unroll
        for (int mi = 0; mi < 4; mi++) {
            int r = m0 + mi*16 + gr;
            a[mi][0] = As[(k0 + gc    )*136 + r];
            a[mi][1] = As[(k0 + gc    )*136 + r + 8];
            a[mi][2] = As[(k0 + gc + 4)*136 + r];
            a[mi][3] = As[(k0 + gc + 4)*136 + r + 8];
        }
        uint bf[4][2];
#pragma unroll
        for (int ni = 0; ni < 4; ni++) {
            int n = n0 + ni*8 + gr;
            bf[ni][0] = Bs1[(k0 + gc    )*136 + n];
            bf[ni][1] = Bs1[(k0 + gc + 4)*136 + n];
        }
#pragma unroll
        for (int mi = 0; mi < 4; mi++)
#pragma unroll
            for (int ni = 0; ni < 4; ni++)
                MMA_TF32(acc1[mi][ni], a[mi], bf[ni]);
    }

    __syncthreads();

#pragma unroll
    for (int mi = 0; mi < 4; mi++)
#pragma unroll
        for (int ni = 0; ni < 4; ni++)
#pragma unroll
            for (int e = 0; e < 4; e++) {
                int row = m0 + mi*16 + gr + (e >> 1)*8;
                int col = n0 + ni*8 + 2*gc + (e & 1);
                float v = gelu_f(acc1[mi][ni][e] + b1s[col]);
                Hs[col*136 + row] = tf32u(v);
            }
    __syncthreads();

    int m0b = warp * 16;
    float acc2[3][4];
#pragma unroll
    for (int ni = 0; ni < 3; ni++)
#pragma unroll
        for (int e = 0; e < 4; e++) acc2[ni][e] = 0.f;

#pragma unroll
    for (int ks = 0; ks < 16; ks++) {
        int k0 = ks * 8;
        uint a[4];
        {
            int r = m0b + gr;
            a[0] = Hs[(k0 + gc    )*136 + r];
            a[1] = Hs[(k0 + gc    )*136 + r + 8];
            a[2] = Hs[(k0 + gc + 4)*136 + r];
            a[3] = Hs[(k0 + gc + 4)*136 + r + 8];
        }
        uint bf[3][2];
#pragma unroll
        for (int ni = 0; ni < 3; ni++) {
            int n = ni*8 + gr;
            bf[ni][0] = Bs2[(k0 + gc    )*40 + n];
            bf[ni][1] = Bs2[(k0 + gc + 4)*40 + n];
        }
#pragma unroll
        for (int ni = 0; ni < 3; ni++)
            MMA_TF32(acc2[ni], a, bf[ni]);
    }

    size_t outbase = (size_t)(b*NCOUT)*NPIX + (size_t)p*256 + w0;
#pragma unroll
    for (int ni = 0; ni < 3; ni++)
#pragma unroll
        for (int e = 0; e < 4; e++) {
            int row = m0b + gr + (e >> 1)*8;
            int col = ni*8 + 2*gc + (e & 1);
            if (col < NCOUT)
                out[outbase + (size_t)col*NPIX + row] = acc2[ni][e] + b2s[col];
        }
}

// ---------------- launch ----------------
extern "C" void kernel_launch(void* const* d_in, const int* in_sizes, int n_in,
                              void* d_out, int out_size) {
    const float* x    = (const float*)d_in[0];
    const float* w1r  = (const float*)d_in[1];
    const float* w1i  = (const float*)d_in[2];
    const float* w2r  = (const float*)d_in[3];
    const float* w2i  = (const float*)d_in[4];
    const float* pw_w = (const float*)d_in[5];
    const float* pw_b = (const float*)d_in[6];
    const float* fc0w = (const float*)d_in[7];
    const float* fc0b = (const float*)d_in[8];
    const float* fc1w = (const float*)d_in[9];
    const float* fc1b = (const float*)d_in[10];
    const float* fc2w = (const float*)d_in[11];
    const float* fc2b = (const float*)d_in[12];
    float* out = (float*)d_out;

    cudaFuncSetAttribute(k_final, cudaFuncAttributeMaxDynamicSharedMemorySize, KF_SMEM_BYTES);
    cudaFuncSetAttribute(k_fc12,  cudaFuncAttributeMaxDynamicSharedMemorySize, KFC_SMEM_BYTES);
    cudaFuncSetAttribute(k_dftw,  cudaFuncAttributeMaxDynamicSharedMemorySize, DFTW_SMEM);

    k_init_tables<<<32, 256>>>();
    k_fc0<<<4096, 256>>>(x, fc0w, fc0b);

    for (int l = 0; l < NLAY; l++) {
        int src = l & 1;
        k_dftw<<<4096, 256, DFTW_SMEM>>>(src);
        k_dfth<<<1024, 256>>>();
        k_modemix<<<512, 256>>>(w1r, w1i, w2r, w2i, l);
        k_idfth<<<1024, 256>>>();
        k_final<<<8192, 256, KF_SMEM_BYTES>>>(src, pw_w, pw_b, l, (l < 3) ? 1 : 0);
    }
    // after l=3 (src=1), result lives in g_h0
    k_fc12<<<8192, 256, KFC_SMEM_BYTES>>>(out, fc1w, fc1b, fc2w, fc2b);
}

// round 13
// speedup vs baseline: 1.6456x; 1.0149x over previous
#include <cuda_runtime.h>
#include <math.h>

// ---------------- problem constants ----------------
#define NB    16
#define NCIN  20
#define NWID  64
#define NPIX  65536      // 256*256
#define NLAY  4
#define M1    16
#define M2    16
#define FCH   128
#define NCOUT 20

typedef unsigned long long ull;
typedef unsigned int uint;

// ---- packed f32x2 helpers ----
__device__ __forceinline__ ull ffma2(ull a, ull b, ull c) {
    ull d; asm("fma.rn.f32x2 %0, %1, %2, %3;" : "=l"(d) : "l"(a), "l"(b), "l"(c)); return d;
}
__device__ __forceinline__ ull add2(ull a, ull b) {
    ull d; asm("add.rn.f32x2 %0, %1, %2;" : "=l"(d) : "l"(a), "l"(b)); return d;
}
__device__ __forceinline__ ull pk2(float lo, float hi) {
    ull r; asm("mov.b64 %0, {%1,%2};" : "=l"(r) : "f"(lo), "f"(hi)); return r;
}
__device__ __forceinline__ float2 up2(ull v) {
    float2 r; asm("mov.b64 {%0,%1}, %2;" : "=f"(r.x), "=f"(r.y) : "l"(v)); return r;
}

// ---- tf32 mma helpers ----
__device__ __forceinline__ uint tf32u(float x) {
    uint y; asm("cvt.rna.tf32.f32 %0, %1;" : "=r"(y) : "f"(x)); return y;
}
#define MMA_TF32(d, a, b) \
    asm volatile("mma.sync.aligned.m16n8k8.row.col.f32.tf32.tf32.f32 " \
                 "{%0,%1,%2,%3}, {%4,%5,%6,%7}, {%8,%9}, {%0,%1,%2,%3};" \
                 : "+f"((d)[0]), "+f"((d)[1]), "+f"((d)[2]), "+f"((d)[3]) \
                 : "r"((a)[0]), "r"((a)[1]), "r"((a)[2]), "r"((a)[3]), \
                   "r"((b)[0]), "r"((b)[1]))

__device__ __forceinline__ float gelu_f(float v) {
    return 0.5f * v * (1.f + erff(v * 0.70710678118654752f));
}

// ---------------- device scratch (no allocations allowed) ----------------
__device__ float  g_h0[NB*NWID*NPIX];          // 256 MB ping
__device__ float  g_h1[NB*NWID*NPIX];          // 256 MB pong
__device__ float2 g_T  [NB*NWID*16*256];       // fwd stage1: [b][i][ky][h]
__device__ float2 g_Xf [32*16*NB*NWID];        // fwd modes:  [kx][ky][b][i]
__device__ float2 g_Xo [NB*NWID*16*32];        // mixed:      [b][o][ky][kx]
__device__ float2 g_Z  [NB*NWID*256*16];       // inv stage1: [b][o][p][ky]
// twiddle tables
__device__ float g_cw[16*256], g_sw[16*256];   // cos/sin(2*pi*ky*w/256)  [ky][w]
__device__ float g_ch[32*256], g_sh[32*256];   // cos/sin(2*pi*kx*h/256)  [k][h]
// folded DFT-W twiddles: rows 0-127: even ky (0,2,..,14), rows 128-255: odd ky.
// col c: ky_class = 2*(c>>1) + (row>=128); value = (c&1) ? -sin(2pi*ky*w/256) : cos
__device__ float g_E2[256*16];

// ---------------- table init ----------------
__global__ __launch_bounds__(256) void k_init_tables() {
    int id = blockIdx.x * 256 + threadIdx.x;   // 8192 threads
    if (id < 16*256) {
        int ky = id >> 8, w = id & 255;
        float s, c;
        sincospif((float)(ky * w) * (1.0f/128.0f), &s, &c);
        g_cw[id] = c; g_sw[id] = s;
    }
    if (id < 32*256) {
        int k = id >> 8, h = id & 255;
        int kx = (k < 16) ? k : (224 + k);
        float s, c;
        sincospif((float)(kx * h) * (1.0f/128.0f), &s, &c);
        g_ch[id] = c; g_sh[id] = s;
    }
    if (id < 256*16) {
        int r = id >> 4, c = id & 15;
        int w = r & 127;
        int ky = 2*(c >> 1) + (r >> 7);
        float s, cv;
        sincospif((float)(ky * w) * (1.0f/128.0f), &s, &cv);
        g_E2[id] = (c & 1) ? -s : cv;
    }
}

// ---------------- lift: h0[b,d,pix] ----------------
__global__ __launch_bounds__(256) void k_fc0(const float* __restrict__ x,
                                             const float* __restrict__ w,
                                             const float* __restrict__ bias) {
    __shared__ float ws[NWID*NCIN];
    __shared__ float bs[NWID];
    int t = threadIdx.x;
    for (int j = t; j < NWID*NCIN; j += 256) ws[j] = w[j];
    if (t < NWID) bs[t] = bias[t];
    __syncthreads();

    int idx = blockIdx.x * 256 + t;
    int b = idx >> 16, pix = idx & 65535;
    ull xin2[10];
#pragma unroll
    for (int q = 0; q < 10; q++) {
        float x0 = x[(size_t)(b*NCIN + 2*q    )*NPIX + pix];
        float x1 = x[(size_t)(b*NCIN + 2*q + 1)*NPIX + pix];
        xin2[q] = pk2(x0, x1);
    }
#pragma unroll 4
    for (int d = 0; d < NWID; d++) {
        const ulonglong2* wp = (const ulonglong2*)(ws + d*NCIN);
        ull a0 = 0ULL, a1 = 0ULL;
#pragma unroll
        for (int q = 0; q < 5; q++) {
            ulonglong2 ww = wp[q];
            a0 = ffma2(xin2[2*q],   ww.x, a0);
            a1 = ffma2(xin2[2*q+1], ww.y, a1);
        }
        float2 u = up2(add2(a0, a1));
        g_h0[(size_t)(b*NWID + d)*NPIX + pix] = u.x + u.y + bs[d];
    }
}

// ---------------- forward DFT over W: radix-2 fold + 3xTF32 split MMA ----------------
// Per block: 64 rows (h of one bi). Even-ky GEMM: F0[64x128] x Ee[128x16];
// odd-ky: F1 x Eo. 3xTF32 split gives near-fp32 accuracy.
#define DFTW_SMEM ((64*260 + 256*24) * 4)
__global__ __launch_bounds__(256) void k_dftw(int srcsel) {
    const float* __restrict__ hin = srcsel ? g_h1 : g_h0;
    extern __shared__ float smf[];
    float* As = smf;              // [row 64][col 256] fp32: cols 0-127 = F0, 128-255 = F1
    float* Bs = smf + 64*260;     // [k 256][n 16] stride 24 fp32
    int t = threadIdx.x, lane = t & 31, warp = t >> 5;
    int gr = lane >> 2, gc = lane & 3;

    const float* hsrc = hin + (size_t)blockIdx.x * 64 * 256;
#pragma unroll
    for (int rr = 0; rr < 8; rr++) {
        int r = warp*8 + rr;
        float4 lo = ((const float4*)(hsrc + r*256))[lane];
        float4 hi = ((const float4*)(hsrc + r*256))[lane + 32];
        float4 F0 = make_float4(lo.x+hi.x, lo.y+hi.y, lo.z+hi.z, lo.w+hi.w);
        float4 F1 = make_float4(lo.x-hi.x, lo.y-hi.y, lo.z-hi.z, lo.w-hi.w);
        *(float4*)(As + r*260 +       lane*4) = F0;
        *(float4*)(As + r*260 + 128 + lane*4) = F1;
    }
#pragma unroll
    for (int rep = 0; rep < 16; rep++) {
        int j = rep*256 + t;      // 4096 entries
        Bs[(j >> 4)*24 + (j & 15)] = g_E2[j];
    }
    __syncthreads();

    int grp = warp >> 2;          // 0: even ky (uses F0 / rows 0-127), 1: odd ky
    int wl  = warp & 3;
    int m0 = (wl & 1) * 32;
    int n0 = (wl >> 1) * 8;
    int kb = grp * 128;

    float accA[2][4] = {}, accB[2][4] = {};
#pragma unroll
    for (int ks = 0; ks < 16; ks++) {
        int k0 = kb + ks*8;
        uint ah[2][4], al[2][4];
#pragma unroll
        for (int mi = 0; mi < 2; mi++) {
            int r = m0 + mi*16 + gr;
#pragma unroll
            for (int j = 0; j < 4; j++) {
                int rr = r + (j & 1)*8;
                int kk = k0 + gc + (j >> 1)*4;
                float v = As[rr*260 + kk];
                uint h = tf32u(v);
                ah[mi][j] = h;
                al[mi][j] = tf32u(v - __uint_as_float(h));
            }
        }
        uint bh[2], bl[2];
#pragma unroll
        for (int j = 0; j < 2; j++) {
            float v = Bs[(k0 + gc + j*4)*24 + n0 + gr];
            uint h = tf32u(v);
            bh[j] = h;
            bl[j] = tf32u(v - __uint_as_float(h));
        }
#pragma unroll
        for (int mi = 0; mi < 2; mi++) {
            MMA_TF32(accA[mi], ah[mi], bh);
            MMA_TF32(accB[mi], ah[mi], bl);
            MMA_TF32(accB[mi], al[mi], bh);
        }
    }

    int bi = blockIdx.x >> 2;
    int h0 = (blockIdx.x & 3) * 64;
    int kyi = (n0 >> 1) + gc;          // 0..7
    int ky  = 2*kyi + grp;
    float2* Tg = g_T + (size_t)bi*4096 + ky*256;
#pragma unroll
    for (int mi = 0; mi < 2; mi++)
#pragma unroll
        for (int ep = 0; ep < 2; ep++) {
            int h = h0 + m0 + mi*16 + gr + ep*8;
            float re = accA[mi][2*ep]   + accB[mi][2*ep];
            float im = accA[mi][2*ep+1] + accB[mi][2*ep+1];
            Tg[h] = make_float2(re, im);
        }
}

// ---------------- forward DFT over H: fp32 rotation + radix-2 fold ----------------
// X[kx] = sum_{h<128} (T[h] + (-1)^kx T[h+128]) e^{-2pi i kx h/256}
__global__ __launch_bounds__(256) void k_dfth() {
    __shared__ float2 Ts[2*2048 + 4];   // even plane at 0, odd plane at 2052 (bank-shifted)
    int bi = blockIdx.x;                // b*64 + i (1024 blocks)
    int t = threadIdx.x;
    const float2* Tg = g_T + (size_t)bi * 4096;
    for (int j = t; j < 2048; j += 256) {
        int ky = j >> 7, h = j & 127;
        float2 u = Tg[ky*256 + h];
        float2 v = Tg[ky*256 + h + 128];
        Ts[j]        = make_float2(u.x + v.x, u.y + v.y);
        Ts[2052 + j] = make_float2(u.x - v.x, u.y - v.y);
    }
    __syncthreads();

    int k  = t & 31;                    // k index: 0-15 -> kx=k, 16-31 -> kx=224+k
    int ky = t >> 5;                    // 0..7; thread also does ky+8
    int b = bi >> 6, i = bi & 63;
    int pb = (k & 1) ? 2052 : 0;        // parity of kx == parity of k

    float c0 = g_ch[k*256 + 1], s0 = g_sh[k*256 + 1];
    float c = 1.f, s = 0.f;
    float re0 = 0.f, im0 = 0.f, re1 = 0.f, im1 = 0.f;
#pragma unroll 4
    for (int h = 0; h < 128; h++) {
        float2 a  = Ts[pb + ky*128 + h];
        float2 bq = Ts[pb + (ky + 8)*128 + h];
        re0 = fmaf(a.x,  c, fmaf( a.y,  s, re0));
        im0 = fmaf(a.y,  c, fmaf(-a.x,  s, im0));
        re1 = fmaf(bq.x, c, fmaf( bq.y, s, re1));
        im1 = fmaf(bq.y, c, fmaf(-bq.x, s, im1));
        float cn = fmaf(-s, s0, c*c0);
        float sn = fmaf( c, s0, s*c0);
        c = cn; s = sn;
    }
    g_Xf[((size_t)(k*16 + ky    )*16 + b)*64 + i] = make_float2(re0, im0);
    g_Xf[((size_t)(k*16 + ky + 8)*16 + b)*64 + i] = make_float2(re1, im1);
}

// ---------------- per-mode complex GEMM ----------------
__global__ __launch_bounds__(256) void k_modemix(const float* __restrict__ w1r, const float* __restrict__ w1i,
                                                 const float* __restrict__ w2r, const float* __restrict__ w2i,
                                                 int layer) {
    __shared__ float2 Xs[16*64];
    __shared__ float2 Ws[64*64];
    int mode = blockIdx.x;
    int kx = mode >> 4, ky = mode & 15;
    int t = threadIdx.x;

    const float2* Xg = g_Xf + (size_t)mode * 1024;
    for (int j = t; j < 1024; j += 256) Xs[j] = Xg[j];

    const float* wr; const float* wi; int kxp;
    if (kx < 16) { wr = w1r; wi = w1i; kxp = kx; }
    else         { wr = w2r; wi = w2i; kxp = kx - 16; }
    size_t base = (size_t)layer * (NWID*NWID*256) + (size_t)kxp*16 + ky;
    for (int j = t; j < 4096; j += 256) {
        Ws[j] = make_float2(wr[base + (size_t)j*256], wi[base + (size_t)j*256]);
    }
    __syncthreads();

#pragma unroll
    for (int r = 0; r < 4; r++) {
        int oid = t + 256*r;
        int b = oid >> 6, o = oid & 63;
        float re = 0.f, im = 0.f;
#pragma unroll 8
        for (int i = 0; i < 64; i++) {
            float2 X = Xs[b*64 + i];
            float2 W = Ws[i*64 + o];
            re = fmaf(X.x, W.x, fmaf(-X.y, W.y, re));
            im = fmaf(X.x, W.y, fmaf( X.y, W.x, im));
        }
        g_Xo[((size_t)(b*64 + o)*16 + ky)*32 + kx] = make_float2(re, im);
    }
}

// ---------------- inverse DFT over H ----------------
__global__ __launch_bounds__(256) void k_idfth() {
    __shared__ float2 Xs[16*32];
    int bo = blockIdx.x;
    int t = threadIdx.x;
    {
        const float4* Xg4 = (const float4*)(g_Xo + (size_t)bo * 512);
        float4* Xs4 = (float4*)Xs;
        for (int j = t; j < 256; j += 256) Xs4[j] = Xg4[j];
    }
    __syncthreads();

    float cth[32], sth[32];
#pragma unroll
    for (int k = 0; k < 32; k++) { cth[k] = g_ch[k*256 + t]; sth[k] = g_sh[k*256 + t]; }

    const float scale = 1.0f / 65536.0f;
#pragma unroll 2
    for (int ky = 0; ky < 16; ky++) {
        float re = 0.f, im = 0.f;
#pragma unroll
        for (int k = 0; k < 32; k++) {
            float2 X = Xs[ky*32 + k];
            re = fmaf(X.x, cth[k], fmaf(-X.y, sth[k], re));
            im = fmaf(X.x, sth[k], fmaf( X.y, cth[k], im));
        }
        g_Z[((size_t)bo*256 + t)*16 + ky] = make_float2(re*scale, im*scale);
    }
}

// ---------------- k_final as tf32 MMA GEMM ----------------
#define KF_SMEM_BYTES ((96*136 + 96*72 + 64) * 4)
__global__ __launch_bounds__(256) void k_final(int srcsel,
                                               const float* __restrict__ pw_w,
                                               const float* __restrict__ pw_b,
                                               int layer, int apply_gelu) {
    const float* __restrict__ hin  = srcsel ? g_h1 : g_h0;
    float*       __restrict__ hout = srcsel ? g_h0 : g_h1;

    extern __shared__ uint smem_u[];
    uint*  As  = smem_u;                       // [k][w] stride 136
    uint*  Bs  = smem_u + 96*136;              // [k][o] stride 72
    float* pbs = (float*)(smem_u + 96*136 + 96*72);

    int t = threadIdx.x;
    int lane = t & 31, warp = t >> 5;
    int bx = blockIdx.x;                       // 8192 = b(16) * p(256) * half(2)
    int b = bx >> 9, p = (bx >> 1) & 255, half = bx & 1;
    int w0 = half * 128;

    const float* hsrc = hin + (size_t)(b*64)*NPIX + (size_t)p*256 + w0;
#pragma unroll
    for (int rr = 0; rr < 8; rr++) {
        int i = warp*8 + rr;
        float4 v = *(const float4*)(hsrc + (size_t)i*NPIX + lane*4);
        uint4 uv = make_uint4(tf32u(v.x), tf32u(v.y), tf32u(v.z), tf32u(v.w));
        *(uint4*)(As + i*136 + lane*4) = uv;
    }
#pragma unroll
    for (int rep = 0; rep < 16; rep++) {
        int j = rep*256 + t;                   // 4096 = e(32) * w(128)
        int e = j >> 7, w = j & 127;
        int q = e >> 1;
        float v = (e & 1) ? -g_sw[q*256 + w0 + w] : g_cw[q*256 + w0 + w];
        As[(64 + e)*136 + w] = tf32u(v);
    }
    const float* pwg = pw_w + (size_t)layer * 4096;
#pragma unroll
    for (int rep = 0; rep < 16; rep++) {
        int j = rep*256 + t;                   // 4096 = o*64 + i
        int o = j >> 6, i = j & 63;
        Bs[i*72 + o] = tf32u(pwg[j]);
    }
#pragma unroll
    for (int rep = 0; rep < 4; rep++) {
        int j = rep*256 + t;                   // 1024 = o*16 + q
        int o = j >> 4, q = j & 15;
        float2 z = g_Z[((size_t)(b*64 + o)*256 + p)*16 + q];
        float a = q ? 2.f : 1.f;
        Bs[(64 + 2*q    )*72 + o] = tf32u(a * z.x);
        Bs[(64 + 2*q + 1)*72 + o] = tf32u(a * z.y);
    }
    if (t < 64) pbs[t] = pw_b[layer*64 + t];
    __syncthreads();

    int warpM = warp & 3, warpN = warp >> 2;
    int m0 = warpM * 32, n0 = warpN * 32;
    int gr = lane >> 2, gc = lane & 3;

    float acc[2][4][4];
#pragma unroll
    for (int mi = 0; mi < 2; mi++)
#pragma unroll
        for (int ni = 0; ni < 4; ni++)
#pragma unroll
            for (int e = 0; e < 4; e++) acc[mi][ni][e] = 0.f;

#pragma unroll
    for (int ks = 0; ks < 12; ks++) {
        int k0 = ks * 8;
        uint a[2][4];
#pragma unroll
        for (int mi = 0; mi < 2; mi++) {
            int r = m0 + mi*16 + gr;
            a[mi][0] = As[(k0 + gc    )*136 + r];
            a[mi][1] = As[(k0 + gc    )*136 + r + 8];
            a[mi][2] = As[(k0 + gc + 4)*136 + r];
            a[mi][3] = As[(k0 + gc + 4)*136 + r + 8];
        }
        uint bf[4][2];
#pragma unroll
        for (int ni = 0; ni < 4; ni++) {
            int n = n0 + ni*8 + gr;
            bf[ni][0] = Bs[(k0 + gc    )*72 + n];
            bf[ni][1] = Bs[(k0 + gc + 4)*72 + n];
        }
#pragma unroll
        for (int mi = 0; mi < 2; mi++)
#pragma unroll
            for (int ni = 0; ni < 4; ni++)
                MMA_TF32(acc[mi][ni], a[mi], bf[ni]);
    }

    size_t outbase = (size_t)(b*64)*NPIX + (size_t)p*256 + w0;
#pragma unroll
    for (int mi = 0; mi < 2; mi++)
#pragma unroll
        for (int ni = 0; ni < 4; ni++)
#pragma unroll
            for (int e = 0; e < 4; e++) {
                int row = m0 + mi*16 + gr + (e >> 1)*8;
                int col = n0 + ni*8 + 2*gc + (e & 1);
                float val = acc[mi][ni][e] + pbs[col];
                if (apply_gelu) val = gelu_f(val);
                hout[outbase + (size_t)col*NPIX + row] = val;
            }
}

// ---------------- fc1+GELU+fc2 as tf32 MMA ----------------
#define KFC_SMEM_BYTES ((128*136 + 128*40 + 128 + 32) * 4)
__global__ __launch_bounds__(256) void k_fc12(float* __restrict__ out,
                                              const float* __restrict__ fc1w, const float* __restrict__ fc1b,
                                              const float* __restrict__ fc2w, const float* __restrict__ fc2b) {
    extern __shared__ uint smem_u[];
    uint*  As  = smem_u;                        // [i][w] stride 136 (k-major)
    uint*  Bs1 = smem_u + 64*136;               // [i][j] stride 136
    uint*  Hs  = smem_u;                        // [j][w] stride 136 (overlaps)
    uint*  Bs2 = smem_u + 128*136;              // [j][o] stride 40
    float* b1s = (float*)(smem_u + 128*136 + 128*40);
    float* b2s = b1s + 128;

    int t = threadIdx.x;
    int lane = t & 31, warp = t >> 5;
    int bx = blockIdx.x;
    int b = bx >> 9, p = (bx >> 1) & 255, half = bx & 1;
    int w0 = half * 128;

    const float* hsrc = g_h0 + (size_t)(b*64)*NPIX + (size_t)p*256 + w0;
#pragma unroll
    for (int rr = 0; rr < 8; rr++) {
        int i = warp*8 + rr;
        float4 v = *(const float4*)(hsrc + (size_t)i*NPIX + lane*4);
        uint4 uv = make_uint4(tf32u(v.x), tf32u(v.y), tf32u(v.z), tf32u(v.w));
        *(uint4*)(As + i*136 + lane*4) = uv;
    }
#pragma unroll
    for (int rep = 0; rep < 32; rep++) {
        int j2 = rep*256 + t;                  // 8192 = j*64 + i
        int jj = j2 >> 6, i = j2 & 63;
        Bs1[i*136 + jj] = tf32u(fc1w[j2]);
    }
#pragma unroll
    for (int rep = 0; rep < 12; rep++) {
        int j2 = rep*256 + t;
        int jj = j2 / 24, o = j2 - jj*24;
        float v = (o < 20) ? fc2w[o*FCH + jj] : 0.f;
        Bs2[jj*40 + o] = tf32u(v);
    }
    if (t < FCH)   b1s[t] = fc1b[t];
    if (t < NCOUT) b2s[t] = fc2b[t];
    __syncthreads();

    int gr = lane >> 2, gc = lane & 3;

    int warpM = warp & 1, warpN = warp >> 1;
    int m0 = warpM * 64, n0 = warpN * 32;
    float acc1[4][4][4];
#pragma unroll
    for (int mi = 0; mi < 4; mi++)
#pragma unroll
        for (int ni = 0; ni < 4; ni++)
#pragma unroll
            for (int e = 0; e < 4; e++) acc1[mi][ni][e] = 0.f;

#pragma unroll
    for (int ks = 0; ks < 8; ks++) {
        int k0 = ks * 8;
        uint a[4][4];
#pragma unroll
        for (int mi = 0; mi < 4; mi++) {
            int r = m0 + mi*16 + gr;
            a[mi][0] = As[(k0 + gc    )*136 + r];
            a[mi][1] = As[(k0 + gc    )*136 + r + 8];
            a[mi][2] = As[(k0 + gc + 4)*136 + r];
            a[mi][3] = As[(k0 + gc + 4)*136 + r + 8];
        }
        uint bf[4][2];
#pragma unroll
        for (int ni = 0; ni < 4; ni++) {
            int n = n0 + ni*8 + gr;
            bf[ni][0] = Bs1[(k0 + gc    )*136 + n];
            bf[ni][1] = Bs1[(k0 + gc + 4)*136 + n];
        }
#pragma unroll
        for (int mi = 0; mi < 4; mi++)
#pragma unroll
            for (int ni = 0; ni < 4; ni++)
                MMA_TF32(acc1[mi][ni], a[mi], bf[ni]);
    }

    __syncthreads();

#pragma unroll
    for (int mi = 0; mi < 4; mi++)
#pragma unroll
        for (int ni = 0; ni < 4; ni++)
#pragma unroll
            for (int e = 0; e < 4; e++) {
                int row = m0 + mi*16 + gr + (e >> 1)*8;
                int col = n0 + ni*8 + 2*gc + (e & 1);
                float v = gelu_f(acc1[mi][ni][e] + b1s[col]);
                Hs[col*136 + row] = tf32u(v);
            }
    __syncthreads();

    int m0b = warp * 16;
    float acc2[3][4];
#pragma unroll
    for (int ni = 0; ni < 3; ni++)
#pragma unroll
        for (int e = 0; e < 4; e++) acc2[ni][e] = 0.f;

#pragma unroll
    for (int ks = 0; ks < 16; ks++) {
        int k0 = ks * 8;
        uint a[4];
        {
            int r = m0b + gr;
            a[0] = Hs[(k0 + gc    )*136 + r];
            a[1] = Hs[(k0 + gc    )*136 + r + 8];
            a[2] = Hs[(k0 + gc + 4)*136 + r];
            a[3] = Hs[(k0 + gc + 4)*136 + r + 8];
        }
        uint bf[3][2];
#pragma unroll
        for (int ni = 0; ni < 3; ni++) {
            int n = ni*8 + gr;
            bf[ni][0] = Bs2[(k0 + gc    )*40 + n];
            bf[ni][1] = Bs2[(k0 + gc + 4)*40 + n];
        }
#pragma unroll
        for (int ni = 0; ni < 3; ni++)
            MMA_TF32(acc2[ni], a, bf[ni]);
    }

    size_t outbase = (size_t)(b*NCOUT)*NPIX + (size_t)p*256 + w0;
#pragma unroll
    for (int ni = 0; ni < 3; ni++)
#pragma unroll
        for (int e = 0; e < 4; e++) {
            int row = m0b + gr + (e >> 1)*8;
            int col = ni*8 + 2*gc + (e & 1);
            if (col < NCOUT)
                out[outbase + (size_t)col*NPIX + row] = acc2[ni][e] + b2s[col];
        }
}

// ---------------- launch ----------------
extern "C" void kernel_launch(void* const* d_in, const int* in_sizes, int n_in,
                              void* d_out, int out_size) {
    const float* x    = (const float*)d_in[0];
    const float* w1r  = (const float*)d_in[1];
    const float* w1i  = (const float*)d_in[2];
    const float* w2r  = (const float*)d_in[3];
    const float* w2i  = (const float*)d_in[4];
    const float* pw_w = (const float*)d_in[5];
    const float* pw_b = (const float*)d_in[6];
    const float* fc0w = (const float*)d_in[7];
    const float* fc0b = (const float*)d_in[8];
    const float* fc1w = (const float*)d_in[9];
    const float* fc1b = (const float*)d_in[10];
    const float* fc2w = (const float*)d_in[11];
    const float* fc2b = (const float*)d_in[12];
    float* out = (float*)d_out;

    cudaFuncSetAttribute(k_final, cudaFuncAttributeMaxDynamicSharedMemorySize, KF_SMEM_BYTES);
    cudaFuncSetAttribute(k_fc12,  cudaFuncAttributeMaxDynamicSharedMemorySize, KFC_SMEM_BYTES);
    cudaFuncSetAttribute(k_dftw,  cudaFuncAttributeMaxDynamicSharedMemorySize, DFTW_SMEM);

    k_init_tables<<<32, 256>>>();
    k_fc0<<<4096, 256>>>(x, fc0w, fc0b);

    for (int l = 0; l < NLAY; l++) {
        int src = l & 1;
        k_dftw<<<4096, 256, DFTW_SMEM>>>(src);
        k_dfth<<<1024, 256>>>();
        k_modemix<<<512, 256>>>(w1r, w1i, w2r, w2i, l);
        k_idfth<<<1024, 256>>>();
        k_final<<<8192, 256, KF_SMEM_BYTES>>>(src, pw_w, pw_b, l, (l < 3) ? 1 : 0);
    }
    // after l=3 (src=1), result lives in g_h0
    k_fc12<<<8192, 256, KFC_SMEM_BYTES>>>(out, fc1w, fc1b, fc2w, fc2b);
}